// round 11
// baseline (speedup 1.0000x reference)
#include <cuda_runtime.h>
#include <cstdint>

// ============================================================================
// SampleNearestNeighborsLayer — exact JAX-semantics replay (bit-exact).
// Per batch b: 4096 sequential steps:
//   minU=min(used); cnt=#(used==minU); r=jax.random.randint(key_q,(),0,cnt)
//   center = r-th least-used point (index order); d_i = ||xyz_i - xyz_c||^2
//   ids = 16 smallest (d,i) lexicographic; used[ids]+=1; used[center]+=100
// Output (float32): idx (8*4096*16) then pts (8*4096*3).
//
// Phase A incremental (hist + per-warp candidate counts maintained by the 17
// atomic counter updates; full rescan only when hist[minU] empties, ~30x).
// Distances in packed f32x2 (two independent rn ops == scalar, bit-exact).
// Threshold T = max of 16 pair-minima (min(wmind[i], wmind[i+16])): 16
// distinct elements <= T certify top-16 in {d<=T}. Bitmask compaction;
// winners by warp-parallel rank (rank = #{key' < key}, keys unique).
// C > CAP (P ~ 5e-3/step) -> exact per-warp pop-16 + merge fallback.
// ============================================================================

#define NQ      4096
#define NPTS    16384
#define KNN     16
#define BATCH   8
#define THREADS 1024
#define NWARP   32
#define CAP     128
#define SMEM_BYTES 232448
#define FULLM   0xFFFFFFFFu

__device__ uint64_t g_hb64[BATCH * NQ + 8];               // +pad for prefetch
__device__ unsigned long long g_fb[BATCH * NWARP * KNN];  // fallback staging

__device__ __forceinline__ uint32_t rotl32(uint32_t x, int r) {
    return (x << r) | (x >> (32 - r));
}

// Threefry-2x32, 20 rounds (JAX schedule) — verified bit-exact on HW.
__device__ __forceinline__ void tf2x32(uint32_t k0, uint32_t k1,
                                       uint32_t x0, uint32_t x1,
                                       uint32_t& o0, uint32_t& o1) {
    uint32_t ks2 = k0 ^ k1 ^ 0x1BD11BDAu;
    x0 += k0; x1 += k1;
#define TFR(r) { x0 += x1; x1 = rotl32(x1, (r)); x1 ^= x0; }
    TFR(13) TFR(15) TFR(26) TFR(6)
    x0 += k1;  x1 += ks2 + 1u;
    TFR(17) TFR(29) TFR(16) TFR(24)
    x0 += ks2; x1 += k0 + 2u;
    TFR(13) TFR(15) TFR(26) TFR(6)
    x0 += k0;  x1 += k1 + 3u;
    TFR(17) TFR(29) TFR(16) TFR(24)
    x0 += k1;  x1 += ks2 + 4u;
    TFR(13) TFR(15) TFR(26) TFR(6)
    x0 += ks2; x1 += k0 + 5u;
#undef TFR
    o0 = x0; o1 = x1;
}

// used[] as u16 pairs in u32 words; word W stored at usw(W) — conflict-free
// for the per-thread contiguous 8-word scan.
__device__ __forceinline__ uint32_t usw(uint32_t W) { return W ^ ((W >> 5) & 31u); }

// Packed pair distance: d = ((dx*dx + dy*dy) + dz*dz) per lane of the f32x2,
// dx = x + (-cx) (IEEE-identical to __fsub_rn). Each f32x2 op is two
// independent round-to-nearest f32 ops -> bit-exact vs scalar.
__device__ __forceinline__ void dist2pair(uint64_t xx, uint64_t yy, uint64_t zz,
                                          uint64_t ncx, uint64_t ncy, uint64_t ncz,
                                          uint32_t& lo, uint32_t& hi) {
    uint64_t dx, dy, dz, sx, sy, szv, t, d;
    asm("add.rn.f32x2 %0, %1, %2;" : "=l"(dx) : "l"(xx), "l"(ncx));
    asm("add.rn.f32x2 %0, %1, %2;" : "=l"(dy) : "l"(yy), "l"(ncy));
    asm("add.rn.f32x2 %0, %1, %2;" : "=l"(dz) : "l"(zz), "l"(ncz));
    asm("mul.rn.f32x2 %0, %1, %2;" : "=l"(sx) : "l"(dx), "l"(dx));
    asm("mul.rn.f32x2 %0, %1, %2;" : "=l"(sy) : "l"(dy), "l"(dy));
    asm("mul.rn.f32x2 %0, %1, %2;" : "=l"(szv) : "l"(dz), "l"(dz));
    asm("add.rn.f32x2 %0, %1, %2;" : "=l"(t) : "l"(sx), "l"(sy));
    asm("add.rn.f32x2 %0, %1, %2;" : "=l"(d) : "l"(t), "l"(szv));
    asm("mov.b64 {%0, %1}, %2;" : "=r"(lo), "=r"(hi) : "l"(d));
}

// Point index for db[j]: pair p = tid + 1024*(j>>1), point = 2p + (j&1).
__device__ __forceinline__ uint32_t didx(uint32_t tid, int j) {
    return 2u * tid + (((uint32_t)j >> 1) << 11) + ((uint32_t)j & 1u);
}

// used[idx] += 1 with exact hist/wcnt2 bookkeeping (transition counted once
// via the atomic's returned old value; values < 4300 << 65536, no carry).
__device__ __forceinline__ void bump1(uint32_t idx, uint32_t minU,
                                      unsigned int* used32,
                                      unsigned int* hist,
                                      unsigned int* wcnt2) {
    uint32_t sh = (idx & 1u) * 16u;
    uint32_t oldw = atomicAdd(&used32[usw(idx >> 1)], 1u << sh);
    uint32_t ov = (oldw >> sh) & 0xFFFFu;
    if (ov < 64u)      atomicSub(&hist[ov], 1u);
    if (ov + 1u < 64u) atomicAdd(&hist[ov + 1u], 1u);
    if (ov == minU)    atomicSub(&wcnt2[idx >> 9], 1u);
}

__device__ __forceinline__ void bump100(uint32_t idx, uint32_t minU,
                                        unsigned int* used32,
                                        unsigned int* hist,
                                        unsigned int* wcnt2) {
    uint32_t sh = (idx & 1u) * 16u;
    uint32_t oldw = atomicAdd(&used32[usw(idx >> 1)], 100u << sh);
    uint32_t ov = (oldw >> sh) & 0xFFFFu;
    if (ov < 64u)   atomicSub(&hist[ov], 1u);   // ov+100 >= 64 always
    if (ov == minU) atomicSub(&wcnt2[idx >> 9], 1u);
}

extern "C" __global__ void __launch_bounds__(THREADS, 1)
snn_kernel(const float* __restrict__ xyz, float* __restrict__ out) {
    extern __shared__ unsigned char smem[];
    float*        vx     = (float*)smem;                      // 64 KB X
    float*        vy     = (float*)(smem + 65536);            // 64 KB Y
    float*        vz     = (float*)(smem + 131072);           // 64 KB Z
    const uint64_t* px   = (const uint64_t*)smem;             // pair views
    const uint64_t* py   = (const uint64_t*)(smem + 65536);
    const uint64_t* pz   = (const uint64_t*)(smem + 131072);
    unsigned int* used32 = (unsigned int*)(smem + 196608);    // 32 KB
    unsigned char* scr   = smem + 229376;                     // 3 KB
    uint64_t*     buf    = (uint64_t*)scr;                    // [128]
    unsigned int* hist   = (unsigned int*)(scr + 1024);       // [64]
    unsigned int* wcnt2  = (unsigned int*)(scr + 1280);       // [32]
    unsigned int* wmind  = (unsigned int*)(scr + 1408);       // [32]
    unsigned int* scnt2  = (unsigned int*)(scr + 1536);       // [2] parity
    unsigned int* sminu  = (unsigned int*)(scr + 1544);
    unsigned int* scen   = (unsigned int*)(scr + 1548);

    const int tid  = threadIdx.x;
    const int b    = blockIdx.x;
    const int lane = tid & 31;
    const int wid  = tid >> 5;

    // ---- init: SoA stage, zero used, RNG bits, phase-A state ----
    const float* g = xyz + (size_t)b * NPTS * 3;
    for (int i = tid; i < NPTS; i += THREADS) {
        vx[i] = g[3*i + 0];
        vy[i] = g[3*i + 1];
        vz[i] = g[3*i + 2];
    }
    for (int i = tid; i < NPTS / 2; i += THREADS) used32[i] = 0u;
    if (tid < 64) hist[tid] = (tid == 0) ? (unsigned)NPTS : 0u;
    if (tid < 32) wcnt2[tid] = NPTS / NWARP;                 // 512 each
    if (tid == 0) { scnt2[0] = 0u; scnt2[1] = 0u; *sminu = 0u; }

    {
        uint32_t bk0, bk1;
        tf2x32(0u, 42u, 0u, (uint32_t)b, bk0, bk1);          // batch key
        for (int q = tid; q < NQ; q += THREADS) {
            uint32_t qk0, qk1, a0, a1, e0, e1, x, y, hb, lb;
            tf2x32(bk0, bk1, 0u, (uint32_t)q, qk0, qk1);     // per-step key
            tf2x32(qk0, qk1, 0u, 0u, a0, a1);                // split[0]
            tf2x32(qk0, qk1, 0u, 1u, e0, e1);                // split[1]
            tf2x32(a0, a1, 0u, 0u, x, y);  hb = x ^ y;
            tf2x32(e0, e1, 0u, 0u, x, y);  lb = x ^ y;
            g_hb64[b*NQ + q] = ((uint64_t)hb << 32) | lb;
        }
    }
    __syncthreads();

    const size_t OUT_PTS = (size_t)BATCH * NQ * KNN;
    uint64_t hb64 = g_hb64[b * NQ];                          // prefetch q=0

    for (int q = 0; q < NQ; ++q) {
        const int gq = b * NQ + q;

        // ================= Phase A (incremental) =================
        uint32_t minU = *sminu;
        uint32_t cnt  = hist[minU];
        if (cnt == 0u) {                                     // rare: ~30 total
            // new minU in (minU, minU+32]: gap <= 29 since min <= mean <= 29
            uint32_t h = hist[minU + 1u + (uint32_t)lane];
            uint32_t mask = __ballot_sync(FULLM, h != 0u);
            uint32_t nm = minU + (uint32_t)__ffs(mask);
            uint32_t mm2 = nm * 0x10001u;
            uint32_t vc = 0u;
            #pragma unroll
            for (int k = 0; k < 8; ++k)
                vc += __vseteq2(used32[usw((uint32_t)tid * 8u + (uint32_t)k)], mm2);
            uint32_t cc = (vc & 0xFFFFu) + (vc >> 16);
            cc = __reduce_add_sync(FULLM, cc);
            if (lane == 0) wcnt2[wid] = cc;
            if (tid == 0) *sminu = nm;
            __syncthreads();                                 // rare bar
            minU = nm;
            cnt = hist[minU];
        }

        // randint (all u32, verified): ((hb%s)*((65536%s)^2%s)+lb%s)%s
        uint32_t rr;
        {
            uint32_t sp = cnt;
            uint32_t hbv = (uint32_t)(hb64 >> 32);
            uint32_t lbv = (uint32_t)hb64;
            uint32_t mlt = 65536u % sp;
            mlt = (mlt * mlt) % sp;
            rr = ((hbv % sp) * mlt + (lbv % sp)) % sp;
        }

        // owner warp from cached per-warp candidate counts
        uint32_t wv = wcnt2[lane];
        uint32_t sc = wv;
        #pragma unroll
        for (int o = 1; o < 32; o <<= 1) {
            uint32_t v = __shfl_up_sync(FULLM, sc, o);
            if (lane >= o) sc += v;
        }
        uint32_t myCnt = __shfl_sync(FULLM, wv, wid);
        uint32_t myPre = __shfl_sync(FULLM, sc, wid) - myCnt;

        if (rr >= myPre && rr < myPre + myCnt) {             // owner warp only
            uint32_t mm2 = minU * 0x10001u;
            uint32_t pw[8];
            uint32_t vc = 0u;
            #pragma unroll
            for (int k = 0; k < 8; ++k) {
                pw[k] = used32[usw((uint32_t)tid * 8u + (uint32_t)k)];
                vc += __vseteq2(pw[k], mm2);
            }
            uint32_t mi = (vc & 0xFFFFu) + (vc >> 16);
            uint32_t li = mi;
            #pragma unroll
            for (int o = 1; o < 32; o <<= 1) {
                uint32_t v = __shfl_up_sync(FULLM, li, o);
                if (lane >= o) li += v;
            }
            uint32_t need = rr - myPre;
            uint32_t le = li - mi;                           // exclusive
            if (need >= le && need < le + mi) {              // winner lane
                uint32_t nd = need - le;
                uint32_t c = 0; bool done = false;
                #pragma unroll
                for (int k = 0; k < 8; ++k) {
                    if (!done && (pw[k] & 0xFFFFu) == minU) {
                        if (nd == 0) { c = (uint32_t)tid*16u + 2u*k; done = true; }
                        else nd--;
                    }
                    if (!done && (pw[k] >> 16) == minU) {
                        if (nd == 0) { c = (uint32_t)tid*16u + 2u*k + 1u; done = true; }
                        else nd--;
                    }
                }
                *scen = c;
                size_t pofs = OUT_PTS + (size_t)gq * 3;
                out[pofs + 0] = vx[c];
                out[pofs + 1] = vy[c];
                out[pofs + 2] = vz[c];
            }
        }
        __syncthreads();                                     // bar1

        // ================= Phase B: packed distances =================
        const uint32_t c = *scen;
        if (tid == 0) scnt2[(q + 1) & 1] = 0u;               // reset next parity
        float cx = vx[c], cy = vy[c], cz = vz[c];
        uint64_t ncx, ncy, ncz;
        {
            float nx = -cx, ny = -cy, nz = -cz;
            asm("mov.b64 %0, {%1, %1};" : "=l"(ncx) : "f"(nx));
            asm("mov.b64 %0, {%1, %1};" : "=l"(ncy) : "f"(ny));
            asm("mov.b64 %0, {%1, %1};" : "=l"(ncz) : "f"(nz));
        }

        uint32_t db[16];
        #pragma unroll
        for (int jp = 0; jp < 8; ++jp) {
            int p = tid + (jp << 10);                        // pair index
            dist2pair(px[p], py[p], pz[p], ncx, ncy, ncz,
                      db[2*jp], db[2*jp + 1]);
        }
        uint32_t tm = db[0];
        #pragma unroll
        for (int j = 1; j < 16; ++j) tm = min(tm, db[j]);
        tm = __reduce_min_sync(FULLM, tm);
        if (lane == 0) wmind[wid] = tm;

        uint64_t hb64n = g_hb64[gq + 1];                     // prefetch next
        __syncthreads();                                     // bar2

        // ====== Phase C: T = max of 16 pair-minima; bitmask compaction ======
        // pm = min(wmind[i], wmind[i+16]) is an element from disjoint warp
        // domains -> 16 distinct elements <= T -> top-16 subset of {d<=T}.
        uint32_t T;
        {
            uint32_t wl = wmind[lane];
            uint32_t pm = min(wl, __shfl_xor_sync(FULLM, wl, 16));
            T = __reduce_max_sync(FULLM, pm);
        }
        unsigned int* cur = &scnt2[q & 1];
        {
            uint32_t hm = 0u;
            #pragma unroll
            for (int j = 0; j < 16; ++j)
                hm |= (db[j] <= T) ? (1u << j) : 0u;
            if (hm) {
                uint32_t n = __popc(hm);
                uint32_t s = atomicAdd(cur, n);
                while (hm) {
                    int j = __ffs(hm) - 1;
                    hm &= hm - 1u;
                    if (s < CAP)
                        buf[s] = ((uint64_t)db[j] << 32) | didx((uint32_t)tid, j);
                    s++;
                }
            }
        }
        __syncthreads();                                     // bar3

        // ====== Phase D: warp-parallel rank -> winners; counter updates =====
        const uint32_t C = scnt2[q & 1];                     // block-uniform
        if (C <= CAP) {
            // element e handled by warp e&31; rank = #{key' < key} (keys
            // unique) == exact top_k position; ranks 0..15 win, in order.
            for (uint32_t e = (uint32_t)wid; e < C; e += 32u) {
                uint64_t key = buf[e];                       // broadcast LDS
                uint32_t rank = 0;
                for (uint32_t base = 0; base < C; base += 32u) {
                    uint32_t slot = base + (uint32_t)lane;
                    uint64_t v = (slot < C) ? buf[slot] : ~0ull;
                    rank += __popc(__ballot_sync(FULLM, v < key));
                }
                if (rank < KNN && (uint32_t)lane == (e >> 5)) {
                    uint32_t myIdx = (uint32_t)key;
                    out[(size_t)gq * KNN + rank] = (float)myIdx;
                    bump1(myIdx, minU, used32, hist, wcnt2);
                }
            }
            if (tid == THREADS - 1)
                bump100(c, minU, used32, hist, wcnt2);
        } else {
            // ===== exact fallback (~5e-3/step): per-warp pop-16 via gmem ====
            uint32_t m1 = FULLM, m2 = FULLM, m3 = FULLM;
            uint32_t j1 = 0, j2 = 0, j3 = 0;
            #pragma unroll
            for (int j = 0; j < 16; ++j) {
                uint32_t v = db[j];
                if (v < m1)      { m3=m2; j3=j2; m2=m1; j2=j1; m1=v; j1=(uint32_t)j; }
                else if (v < m2) { m3=m2; j3=j2; m2=v; j2=(uint32_t)j; }
                else if (v < m3) { m3=v; j3=(uint32_t)j; }
            }
            uint32_t popped = 0;
            #pragma unroll 1
            for (int it = 0; it < KNN; ++it) {
                uint32_t wmin = __reduce_min_sync(FULLM, m1);
                uint32_t cand = (m1 == wmin) ? didx((uint32_t)tid, (int)j1) : FULLM;
                uint32_t imin = __reduce_min_sync(FULLM, cand);
                if (cand == imin) {
                    popped |= 1u << j1;
                    if (m2 != FULLM) { m1=m2; j1=j2; m2=m3; j2=j3; m3=FULLM; }
                    else {
                        m1 = m2 = m3 = FULLM; j1 = j2 = j3 = 0;
                        #pragma unroll
                        for (int j = 0; j < 16; ++j) {
                            uint32_t v = ((popped >> j) & 1u) ? FULLM : db[j];
                            if (v < m1)      { m3=m2; j3=j2; m2=m1; j2=j1; m1=v; j1=(uint32_t)j; }
                            else if (v < m2) { m3=m2; j3=j2; m2=v; j2=(uint32_t)j; }
                            else if (v < m3) { m3=v; j3=(uint32_t)j; }
                        }
                    }
                }
                if (lane == 0)
                    g_fb[(b * NWARP + wid) * KNN + it] =
                        ((unsigned long long)wmin << 32) | imin;
            }
            __syncthreads();     // uniform branch; orders g_fb for warp 0
            if (wid == 0) {
                int pos = 0;
                uint64_t head = g_fb[(b * NWARP + lane) * KNN];
                uint32_t myIdx = 0;
                #pragma unroll 1
                for (int it = 0; it < KNN; ++it) {
                    uint32_t hD = (uint32_t)(head >> 32);
                    uint32_t wmin = __reduce_min_sync(FULLM, hD);
                    uint32_t cand = (hD == wmin) ? (uint32_t)head : FULLM;
                    uint32_t imin = __reduce_min_sync(FULLM, cand);
                    if (cand == imin) {
                        pos++;
                        head = (pos < KNN)
                             ? g_fb[(b * NWARP + lane) * KNN + pos] : ~0ull;
                    }
                    if (lane == it) myIdx = imin;
                }
                if (lane < KNN) {
                    out[(size_t)gq * KNN + lane] = (float)myIdx;
                    bump1(myIdx, minU, used32, hist, wcnt2);
                }
                if (lane == KNN)
                    bump100(c, minU, used32, hist, wcnt2);
            }
        }
        __syncthreads();                                     // bar4
        hb64 = hb64n;
    }
}

extern "C" void kernel_launch(void* const* d_in, const int* in_sizes, int n_in,
                              void* d_out, int out_size) {
    (void)in_sizes; (void)n_in; (void)out_size;
    cudaFuncSetAttribute(snn_kernel,
                         cudaFuncAttributeMaxDynamicSharedMemorySize, SMEM_BYTES);
    snn_kernel<<<BATCH, THREADS, SMEM_BYTES>>>((const float*)d_in[0], (float*)d_out);
}

// round 12
// speedup vs baseline: 1.0078x; 1.0078x over previous
#include <cuda_runtime.h>
#include <cstdint>

// ============================================================================
// SampleNearestNeighborsLayer — exact JAX-semantics replay (bit-exact).
// Per batch b: 4096 sequential steps:
//   minU=min(used); cnt=#(used==minU); r=jax.random.randint(key_q,(),0,cnt)
//   center = r-th least-used point (index order); d_i = ||xyz_i - xyz_c||^2
//   ids = 16 smallest (d,i) lexicographic; used[ids]+=1; used[center]+=100
// Output (float32): idx (8*4096*16) then pts (8*4096*3).
//
// Phase A incremental (hist + per-warp candidate counts maintained by the 17
// atomic counter updates; full rescan only when hist[minU] empties, ~30x).
// randint mods via exact Barrett reduction (one udiv + mulhi-based mods).
// Distances in packed f32x2 (two independent rn ops == scalar, bit-exact).
// Threshold T = max of 16 pair-minima: 16 distinct elements <= T certify
// top-16 in {d<=T}. Bitmask compaction; per-thread parallel rank (rank r ==
// r-th smallest, keys unique). C > CAP (P~5e-3/step) -> exact fallback.
// ============================================================================

#define NQ      4096
#define NPTS    16384
#define KNN     16
#define BATCH   8
#define THREADS 1024
#define NWARP   32
#define CAP     128
#define SMEM_BYTES 232448
#define FULLM   0xFFFFFFFFu

__device__ uint64_t g_hb64[BATCH * NQ + 8];               // +pad for prefetch
__device__ unsigned long long g_fb[BATCH * NWARP * KNN];  // fallback staging

__device__ __forceinline__ uint32_t rotl32(uint32_t x, int r) {
    return (x << r) | (x >> (32 - r));
}

// Threefry-2x32, 20 rounds (JAX schedule) — verified bit-exact on HW.
__device__ __forceinline__ void tf2x32(uint32_t k0, uint32_t k1,
                                       uint32_t x0, uint32_t x1,
                                       uint32_t& o0, uint32_t& o1) {
    uint32_t ks2 = k0 ^ k1 ^ 0x1BD11BDAu;
    x0 += k0; x1 += k1;
#define TFR(r) { x0 += x1; x1 = rotl32(x1, (r)); x1 ^= x0; }
    TFR(13) TFR(15) TFR(26) TFR(6)
    x0 += k1;  x1 += ks2 + 1u;
    TFR(17) TFR(29) TFR(16) TFR(24)
    x0 += ks2; x1 += k0 + 2u;
    TFR(13) TFR(15) TFR(26) TFR(6)
    x0 += k0;  x1 += k1 + 3u;
    TFR(17) TFR(29) TFR(16) TFR(24)
    x0 += k1;  x1 += ks2 + 4u;
    TFR(13) TFR(15) TFR(26) TFR(6)
    x0 += ks2; x1 += k0 + 5u;
#undef TFR
    o0 = x0; o1 = x1;
}

// used[] as u16 pairs in u32 words; word W stored at usw(W) — conflict-free
// for the per-thread contiguous 8-word scan.
__device__ __forceinline__ uint32_t usw(uint32_t W) { return W ^ ((W >> 5) & 31u); }

// Exact x mod s via Barrett: m = (2^32-1)/s ensures floor(x/s)-3 <= q <=
// floor(x/s), so r = x - q*s in [x mod s, x mod s + 3s] -> <=4 cond subs.
__device__ __forceinline__ uint32_t umodb(uint32_t x, uint32_t s, uint32_t m) {
    uint32_t q = __umulhi(x, m);
    uint32_t r = x - q * s;
    #pragma unroll
    for (int i = 0; i < 4; ++i) if (r >= s) r -= s;
    return r;
}

// Packed pair distance: d = ((dx*dx + dy*dy) + dz*dz) per lane of the f32x2,
// dx = x + (-cx) (IEEE-identical to __fsub_rn). Each f32x2 op is two
// independent round-to-nearest f32 ops -> bit-exact vs scalar.
__device__ __forceinline__ void dist2pair(uint64_t xx, uint64_t yy, uint64_t zz,
                                          uint64_t ncx, uint64_t ncy, uint64_t ncz,
                                          uint32_t& lo, uint32_t& hi) {
    uint64_t dx, dy, dz, sx, sy, szv, t, d;
    asm("add.rn.f32x2 %0, %1, %2;" : "=l"(dx) : "l"(xx), "l"(ncx));
    asm("add.rn.f32x2 %0, %1, %2;" : "=l"(dy) : "l"(yy), "l"(ncy));
    asm("add.rn.f32x2 %0, %1, %2;" : "=l"(dz) : "l"(zz), "l"(ncz));
    asm("mul.rn.f32x2 %0, %1, %2;" : "=l"(sx) : "l"(dx), "l"(dx));
    asm("mul.rn.f32x2 %0, %1, %2;" : "=l"(sy) : "l"(dy), "l"(dy));
    asm("mul.rn.f32x2 %0, %1, %2;" : "=l"(szv) : "l"(dz), "l"(dz));
    asm("add.rn.f32x2 %0, %1, %2;" : "=l"(t) : "l"(sx), "l"(sy));
    asm("add.rn.f32x2 %0, %1, %2;" : "=l"(d) : "l"(t), "l"(szv));
    asm("mov.b64 {%0, %1}, %2;" : "=r"(lo), "=r"(hi) : "l"(d));
}

// Point index for db[j]: pair p = tid + 1024*(j>>1), point = 2p + (j&1).
__device__ __forceinline__ uint32_t didx(uint32_t tid, int j) {
    return 2u * tid + (((uint32_t)j >> 1) << 11) + ((uint32_t)j & 1u);
}

// used[idx] += 1 with exact hist/wcnt2 bookkeeping (transition counted once
// via the atomic's returned old value; values < 4300 << 65536, no carry).
__device__ __forceinline__ void bump1(uint32_t idx, uint32_t minU,
                                      unsigned int* used32,
                                      unsigned int* hist,
                                      unsigned int* wcnt2) {
    uint32_t sh = (idx & 1u) * 16u;
    uint32_t oldw = atomicAdd(&used32[usw(idx >> 1)], 1u << sh);
    uint32_t ov = (oldw >> sh) & 0xFFFFu;
    if (ov < 64u)      atomicSub(&hist[ov], 1u);
    if (ov + 1u < 64u) atomicAdd(&hist[ov + 1u], 1u);
    if (ov == minU)    atomicSub(&wcnt2[idx >> 9], 1u);
}

__device__ __forceinline__ void bump100(uint32_t idx, uint32_t minU,
                                        unsigned int* used32,
                                        unsigned int* hist,
                                        unsigned int* wcnt2) {
    uint32_t sh = (idx & 1u) * 16u;
    uint32_t oldw = atomicAdd(&used32[usw(idx >> 1)], 100u << sh);
    uint32_t ov = (oldw >> sh) & 0xFFFFu;
    if (ov < 64u)   atomicSub(&hist[ov], 1u);   // ov+100 >= 64 always
    if (ov == minU) atomicSub(&wcnt2[idx >> 9], 1u);
}

extern "C" __global__ void __launch_bounds__(THREADS, 1)
snn_kernel(const float* __restrict__ xyz, float* __restrict__ out) {
    extern __shared__ unsigned char smem[];
    float*        vx     = (float*)smem;                      // 64 KB X
    float*        vy     = (float*)(smem + 65536);            // 64 KB Y
    float*        vz     = (float*)(smem + 131072);           // 64 KB Z
    const uint64_t* px   = (const uint64_t*)smem;             // pair views
    const uint64_t* py   = (const uint64_t*)(smem + 65536);
    const uint64_t* pz   = (const uint64_t*)(smem + 131072);
    unsigned int* used32 = (unsigned int*)(smem + 196608);    // 32 KB
    unsigned char* scr   = smem + 229376;                     // 3 KB
    uint64_t*     buf    = (uint64_t*)scr;                    // [128]
    unsigned int* hist   = (unsigned int*)(scr + 1024);       // [64]
    unsigned int* wcnt2  = (unsigned int*)(scr + 1280);       // [32]
    unsigned int* wmind  = (unsigned int*)(scr + 1408);       // [32]
    unsigned int* scnt2  = (unsigned int*)(scr + 1536);       // [2] parity
    unsigned int* sminu  = (unsigned int*)(scr + 1544);
    unsigned int* scen   = (unsigned int*)(scr + 1548);

    const int tid  = threadIdx.x;
    const int b    = blockIdx.x;
    const int lane = tid & 31;
    const int wid  = tid >> 5;

    // ---- init: SoA stage, zero used, RNG bits, phase-A state ----
    const float* g = xyz + (size_t)b * NPTS * 3;
    for (int i = tid; i < NPTS; i += THREADS) {
        vx[i] = g[3*i + 0];
        vy[i] = g[3*i + 1];
        vz[i] = g[3*i + 2];
    }
    for (int i = tid; i < NPTS / 2; i += THREADS) used32[i] = 0u;
    if (tid < 64) hist[tid] = (tid == 0) ? (unsigned)NPTS : 0u;
    if (tid < 32) wcnt2[tid] = NPTS / NWARP;                 // 512 each
    if (tid == 0) { scnt2[0] = 0u; scnt2[1] = 0u; *sminu = 0u; }

    {
        uint32_t bk0, bk1;
        tf2x32(0u, 42u, 0u, (uint32_t)b, bk0, bk1);          // batch key
        for (int q = tid; q < NQ; q += THREADS) {
            uint32_t qk0, qk1, a0, a1, e0, e1, x, y, hb, lb;
            tf2x32(bk0, bk1, 0u, (uint32_t)q, qk0, qk1);     // per-step key
            tf2x32(qk0, qk1, 0u, 0u, a0, a1);                // split[0]
            tf2x32(qk0, qk1, 0u, 1u, e0, e1);                // split[1]
            tf2x32(a0, a1, 0u, 0u, x, y);  hb = x ^ y;
            tf2x32(e0, e1, 0u, 0u, x, y);  lb = x ^ y;
            g_hb64[b*NQ + q] = ((uint64_t)hb << 32) | lb;
        }
    }
    __syncthreads();

    const size_t OUT_PTS = (size_t)BATCH * NQ * KNN;
    uint64_t hb64 = g_hb64[b * NQ];                          // prefetch q=0

    for (int q = 0; q < NQ; ++q) {
        const int gq = b * NQ + q;

        // ================= Phase A (incremental) =================
        uint32_t minU = *sminu;
        uint32_t cnt  = hist[minU];
        if (cnt == 0u) {                                     // rare: ~30 total
            // new minU in (minU, minU+32]: gap <= 29 since min <= mean <= 29
            uint32_t h = hist[minU + 1u + (uint32_t)lane];
            uint32_t mask = __ballot_sync(FULLM, h != 0u);
            uint32_t nm = minU + (uint32_t)__ffs(mask);
            uint32_t mm2 = nm * 0x10001u;
            uint32_t vc = 0u;
            #pragma unroll
            for (int k = 0; k < 8; ++k)
                vc += __vseteq2(used32[usw((uint32_t)tid * 8u + (uint32_t)k)], mm2);
            uint32_t cc = (vc & 0xFFFFu) + (vc >> 16);
            cc = __reduce_add_sync(FULLM, cc);
            if (lane == 0) wcnt2[wid] = cc;
            if (tid == 0) *sminu = nm;
            __syncthreads();                                 // rare bar
            minU = nm;
            cnt = hist[minU];
        }

        // randint (exact Barrett mods): ((hb%s)*((65536%s)^2%s)+lb%s)%s
        uint32_t rr;
        {
            uint32_t sp = cnt;
            uint32_t m = 0xFFFFFFFFu / sp;                   // Barrett factor
            uint32_t hbv = (uint32_t)(hb64 >> 32);
            uint32_t lbv = (uint32_t)hb64;
            uint32_t t65 = umodb(65536u, sp, m);
            uint32_t mlt = umodb(t65 * t65, sp, m);          // t65^2 < 2^28
            uint32_t am  = umodb(hbv, sp, m);
            uint32_t bm  = umodb(lbv, sp, m);
            rr = umodb(am * mlt + bm, sp, m);                // < 2^28 + 2^14
        }

        // owner warp from cached per-warp candidate counts
        uint32_t wv = wcnt2[lane];
        uint32_t sc = wv;
        #pragma unroll
        for (int o = 1; o < 32; o <<= 1) {
            uint32_t v = __shfl_up_sync(FULLM, sc, o);
            if (lane >= o) sc += v;
        }
        uint32_t myCnt = __shfl_sync(FULLM, wv, wid);
        uint32_t myPre = __shfl_sync(FULLM, sc, wid) - myCnt;

        if (rr >= myPre && rr < myPre + myCnt) {             // owner warp only
            uint32_t mm2 = minU * 0x10001u;
            uint32_t pw[8];
            uint32_t vc = 0u;
            #pragma unroll
            for (int k = 0; k < 8; ++k) {
                pw[k] = used32[usw((uint32_t)tid * 8u + (uint32_t)k)];
                vc += __vseteq2(pw[k], mm2);
            }
            uint32_t mi = (vc & 0xFFFFu) + (vc >> 16);
            uint32_t li = mi;
            #pragma unroll
            for (int o = 1; o < 32; o <<= 1) {
                uint32_t v = __shfl_up_sync(FULLM, li, o);
                if (lane >= o) li += v;
            }
            uint32_t need = rr - myPre;
            uint32_t le = li - mi;                           // exclusive
            if (need >= le && need < le + mi) {              // winner lane
                uint32_t nd = need - le;
                uint32_t c = 0; bool done = false;
                #pragma unroll
                for (int k = 0; k < 8; ++k) {
                    if (!done && (pw[k] & 0xFFFFu) == minU) {
                        if (nd == 0) { c = (uint32_t)tid*16u + 2u*k; done = true; }
                        else nd--;
                    }
                    if (!done && (pw[k] >> 16) == minU) {
                        if (nd == 0) { c = (uint32_t)tid*16u + 2u*k + 1u; done = true; }
                        else nd--;
                    }
                }
                *scen = c;
                size_t pofs = OUT_PTS + (size_t)gq * 3;
                out[pofs + 0] = vx[c];
                out[pofs + 1] = vy[c];
                out[pofs + 2] = vz[c];
            }
        }
        __syncthreads();                                     // bar1

        // ================= Phase B: packed distances =================
        const uint32_t c = *scen;
        if (tid == 0) scnt2[(q + 1) & 1] = 0u;               // reset next parity
        float cx = vx[c], cy = vy[c], cz = vz[c];
        uint64_t ncx, ncy, ncz;
        {
            float nx = -cx, ny = -cy, nz = -cz;
            asm("mov.b64 %0, {%1, %1};" : "=l"(ncx) : "f"(nx));
            asm("mov.b64 %0, {%1, %1};" : "=l"(ncy) : "f"(ny));
            asm("mov.b64 %0, {%1, %1};" : "=l"(ncz) : "f"(nz));
        }

        uint32_t db[16];
        #pragma unroll
        for (int jp = 0; jp < 8; ++jp) {
            int p = tid + (jp << 10);                        // pair index
            dist2pair(px[p], py[p], pz[p], ncx, ncy, ncz,
                      db[2*jp], db[2*jp + 1]);
        }
        uint32_t tm = db[0];
        #pragma unroll
        for (int j = 1; j < 16; ++j) tm = min(tm, db[j]);
        tm = __reduce_min_sync(FULLM, tm);
        if (lane == 0) wmind[wid] = tm;

        uint64_t hb64n = g_hb64[gq + 1];                     // prefetch next
        __syncthreads();                                     // bar2

        // ====== Phase C: T = max of 16 pair-minima; bitmask compaction ======
        // pm = min(wmind[i], wmind[i+16]) is an element from disjoint warp
        // domains -> 16 distinct elements <= T -> top-16 subset of {d<=T}.
        uint32_t T;
        {
            uint32_t wl = wmind[lane];
            uint32_t pm = min(wl, __shfl_xor_sync(FULLM, wl, 16));
            T = __reduce_max_sync(FULLM, pm);
        }
        unsigned int* cur = &scnt2[q & 1];
        {
            uint32_t hm = 0u;
            #pragma unroll
            for (int j = 0; j < 16; ++j)
                hm |= (db[j] <= T) ? (1u << j) : 0u;
            if (hm) {
                uint32_t n = __popc(hm);
                uint32_t s = atomicAdd(cur, n);
                while (hm) {
                    int j = __ffs(hm) - 1;
                    hm &= hm - 1u;
                    if (s < CAP)
                        buf[s] = ((uint64_t)db[j] << 32) | didx((uint32_t)tid, j);
                    s++;
                }
            }
        }
        __syncthreads();                                     // bar3

        // ====== Phase D: per-thread parallel rank (round-10 proven) =========
        const uint32_t C = scnt2[q & 1];                     // block-uniform
        if (C <= CAP) {
            if ((uint32_t)tid < C) {
                uint64_t my = buf[tid];
                uint32_t rank = 0;
                int j = 0;
                for (; j + 4 <= (int)C; j += 4) {
                    rank += (uint32_t)(buf[j]     < my);
                    rank += (uint32_t)(buf[j + 1] < my);
                    rank += (uint32_t)(buf[j + 2] < my);
                    rank += (uint32_t)(buf[j + 3] < my);
                }
                for (; j < (int)C; ++j) rank += (uint32_t)(buf[j] < my);
                if (rank < KNN) {
                    uint32_t myIdx = (uint32_t)my;
                    out[(size_t)gq * KNN + rank] = (float)myIdx;
                    bump1(myIdx, minU, used32, hist, wcnt2);
                }
            }
            if (tid == THREADS - 1)
                bump100(c, minU, used32, hist, wcnt2);
        } else {
            // ===== exact fallback (~5e-3/step): per-warp pop-16 via gmem ====
            uint32_t m1 = FULLM, m2 = FULLM, m3 = FULLM;
            uint32_t j1 = 0, j2 = 0, j3 = 0;
            #pragma unroll
            for (int j = 0; j < 16; ++j) {
                uint32_t v = db[j];
                if (v < m1)      { m3=m2; j3=j2; m2=m1; j2=j1; m1=v; j1=(uint32_t)j; }
                else if (v < m2) { m3=m2; j3=j2; m2=v; j2=(uint32_t)j; }
                else if (v < m3) { m3=v; j3=(uint32_t)j; }
            }
            uint32_t popped = 0;
            #pragma unroll 1
            for (int it = 0; it < KNN; ++it) {
                uint32_t wmin = __reduce_min_sync(FULLM, m1);
                uint32_t cand = (m1 == wmin) ? didx((uint32_t)tid, (int)j1) : FULLM;
                uint32_t imin = __reduce_min_sync(FULLM, cand);
                if (cand == imin) {
                    popped |= 1u << j1;
                    if (m2 != FULLM) { m1=m2; j1=j2; m2=m3; j2=j3; m3=FULLM; }
                    else {
                        m1 = m2 = m3 = FULLM; j1 = j2 = j3 = 0;
                        #pragma unroll
                        for (int j = 0; j < 16; ++j) {
                            uint32_t v = ((popped >> j) & 1u) ? FULLM : db[j];
                            if (v < m1)      { m3=m2; j3=j2; m2=m1; j2=j1; m1=v; j1=(uint32_t)j; }
                            else if (v < m2) { m3=m2; j3=j2; m2=v; j2=(uint32_t)j; }
                            else if (v < m3) { m3=v; j3=(uint32_t)j; }
                        }
                    }
                }
                if (lane == 0)
                    g_fb[(b * NWARP + wid) * KNN + it] =
                        ((unsigned long long)wmin << 32) | imin;
            }
            __syncthreads();     // uniform branch; orders g_fb for warp 0
            if (wid == 0) {
                int pos = 0;
                uint64_t head = g_fb[(b * NWARP + lane) * KNN];
                uint32_t myIdx = 0;
                #pragma unroll 1
                for (int it = 0; it < KNN; ++it) {
                    uint32_t hD = (uint32_t)(head >> 32);
                    uint32_t wmin = __reduce_min_sync(FULLM, hD);
                    uint32_t cand = (hD == wmin) ? (uint32_t)head : FULLM;
                    uint32_t imin = __reduce_min_sync(FULLM, cand);
                    if (cand == imin) {
                        pos++;
                        head = (pos < KNN)
                             ? g_fb[(b * NWARP + lane) * KNN + pos] : ~0ull;
                    }
                    if (lane == it) myIdx = imin;
                }
                if (lane < KNN) {
                    out[(size_t)gq * KNN + lane] = (float)myIdx;
                    bump1(myIdx, minU, used32, hist, wcnt2);
                }
                if (lane == KNN)
                    bump100(c, minU, used32, hist, wcnt2);
            }
        }
        __syncthreads();                                     // bar4
        hb64 = hb64n;
    }
}

extern "C" void kernel_launch(void* const* d_in, const int* in_sizes, int n_in,
                              void* d_out, int out_size) {
    (void)in_sizes; (void)n_in; (void)out_size;
    cudaFuncSetAttribute(snn_kernel,
                         cudaFuncAttributeMaxDynamicSharedMemorySize, SMEM_BYTES);
    snn_kernel<<<BATCH, THREADS, SMEM_BYTES>>>((const float*)d_in[0], (float*)d_out);
}

// round 13
// speedup vs baseline: 1.2046x; 1.1954x over previous
#include <cuda_runtime.h>
#include <cstdint>

// ============================================================================
// SampleNearestNeighborsLayer — exact JAX-semantics replay (bit-exact).
// Per batch b: 4096 sequential steps:
//   minU=min(used); cnt=#(used==minU); r=jax.random.randint(key_q,(),0,cnt)
//   center = r-th least-used point (index order); d_i = ||xyz_i - xyz_c||^2
//   ids = 16 smallest (d,i) lexicographic; used[ids]+=1; used[center]+=100
// Output (float32): idx (8*4096*16) then pts (8*4096*3).
//
// == Round-10 kernel (best: 14.07 ms) with ONE change: Barrett randint. ==
// Phase A incremental (hist + per-warp candidate counts maintained by the 17
// atomic counter updates; full rescan only when hist[minU] empties, ~30x).
// Distances in packed f32x2 (two independent rn ops == scalar, bit-exact).
// Threshold T = max of 16 pair-minima: 16 distinct elements <= T certify
// top-16 in {d<=T}. Per-hit atomic compaction (round-10 form); per-thread
// parallel rank. C > CAP (P~5e-3/step) -> exact fallback.
// ============================================================================

#define NQ      4096
#define NPTS    16384
#define KNN     16
#define BATCH   8
#define THREADS 1024
#define NWARP   32
#define CAP     128
#define SMEM_BYTES 232448
#define FULLM   0xFFFFFFFFu

__device__ uint64_t g_hb64[BATCH * NQ + 8];               // +pad for prefetch
__device__ unsigned long long g_fb[BATCH * NWARP * KNN];  // fallback staging

__device__ __forceinline__ uint32_t rotl32(uint32_t x, int r) {
    return (x << r) | (x >> (32 - r));
}

// Threefry-2x32, 20 rounds (JAX schedule) — verified bit-exact on HW.
__device__ __forceinline__ void tf2x32(uint32_t k0, uint32_t k1,
                                       uint32_t x0, uint32_t x1,
                                       uint32_t& o0, uint32_t& o1) {
    uint32_t ks2 = k0 ^ k1 ^ 0x1BD11BDAu;
    x0 += k0; x1 += k1;
#define TFR(r) { x0 += x1; x1 = rotl32(x1, (r)); x1 ^= x0; }
    TFR(13) TFR(15) TFR(26) TFR(6)
    x0 += k1;  x1 += ks2 + 1u;
    TFR(17) TFR(29) TFR(16) TFR(24)
    x0 += ks2; x1 += k0 + 2u;
    TFR(13) TFR(15) TFR(26) TFR(6)
    x0 += k0;  x1 += k1 + 3u;
    TFR(17) TFR(29) TFR(16) TFR(24)
    x0 += k1;  x1 += ks2 + 4u;
    TFR(13) TFR(15) TFR(26) TFR(6)
    x0 += ks2; x1 += k0 + 5u;
#undef TFR
    o0 = x0; o1 = x1;
}

// used[] as u16 pairs in u32 words; word W stored at usw(W) — conflict-free
// for the per-thread contiguous 8-word scan.
__device__ __forceinline__ uint32_t usw(uint32_t W) { return W ^ ((W >> 5) & 31u); }

// Exact x mod s via Barrett: m = (2^32-1)/s gives floor(x/s)-3 <= q <=
// floor(x/s), so r = x - q*s in [x mod s, x mod s + 3s] -> <=4 cond subs.
__device__ __forceinline__ uint32_t umodb(uint32_t x, uint32_t s, uint32_t m) {
    uint32_t q = __umulhi(x, m);
    uint32_t r = x - q * s;
    #pragma unroll
    for (int i = 0; i < 4; ++i) if (r >= s) r -= s;
    return r;
}

// Packed pair distance: d = ((dx*dx + dy*dy) + dz*dz) per lane of the f32x2,
// dx = x + (-cx) (IEEE-identical to __fsub_rn). Each f32x2 op is two
// independent round-to-nearest f32 ops -> bit-exact vs scalar.
__device__ __forceinline__ void dist2pair(uint64_t xx, uint64_t yy, uint64_t zz,
                                          uint64_t ncx, uint64_t ncy, uint64_t ncz,
                                          uint32_t& lo, uint32_t& hi) {
    uint64_t dx, dy, dz, sx, sy, szv, t, d;
    asm("add.rn.f32x2 %0, %1, %2;" : "=l"(dx) : "l"(xx), "l"(ncx));
    asm("add.rn.f32x2 %0, %1, %2;" : "=l"(dy) : "l"(yy), "l"(ncy));
    asm("add.rn.f32x2 %0, %1, %2;" : "=l"(dz) : "l"(zz), "l"(ncz));
    asm("mul.rn.f32x2 %0, %1, %2;" : "=l"(sx) : "l"(dx), "l"(dx));
    asm("mul.rn.f32x2 %0, %1, %2;" : "=l"(sy) : "l"(dy), "l"(dy));
    asm("mul.rn.f32x2 %0, %1, %2;" : "=l"(szv) : "l"(dz), "l"(dz));
    asm("add.rn.f32x2 %0, %1, %2;" : "=l"(t) : "l"(sx), "l"(sy));
    asm("add.rn.f32x2 %0, %1, %2;" : "=l"(d) : "l"(t), "l"(szv));
    asm("mov.b64 {%0, %1}, %2;" : "=r"(lo), "=r"(hi) : "l"(d));
}

// Point index for db[j]: pair p = tid + 1024*(j>>1), point = 2p + (j&1).
__device__ __forceinline__ uint32_t didx(uint32_t tid, int j) {
    return 2u * tid + (((uint32_t)j >> 1) << 11) + ((uint32_t)j & 1u);
}

// used[idx] += 1 with exact hist/wcnt2 bookkeeping (transition counted once
// via the atomic's returned old value; values < 4300 << 65536, no carry).
__device__ __forceinline__ void bump1(uint32_t idx, uint32_t minU,
                                      unsigned int* used32,
                                      unsigned int* hist,
                                      unsigned int* wcnt2) {
    uint32_t sh = (idx & 1u) * 16u;
    uint32_t oldw = atomicAdd(&used32[usw(idx >> 1)], 1u << sh);
    uint32_t ov = (oldw >> sh) & 0xFFFFu;
    if (ov < 64u)      atomicSub(&hist[ov], 1u);
    if (ov + 1u < 64u) atomicAdd(&hist[ov + 1u], 1u);
    if (ov == minU)    atomicSub(&wcnt2[idx >> 9], 1u);
}

__device__ __forceinline__ void bump100(uint32_t idx, uint32_t minU,
                                        unsigned int* used32,
                                        unsigned int* hist,
                                        unsigned int* wcnt2) {
    uint32_t sh = (idx & 1u) * 16u;
    uint32_t oldw = atomicAdd(&used32[usw(idx >> 1)], 100u << sh);
    uint32_t ov = (oldw >> sh) & 0xFFFFu;
    if (ov < 64u)   atomicSub(&hist[ov], 1u);   // ov+100 >= 64 always
    if (ov == minU) atomicSub(&wcnt2[idx >> 9], 1u);
}

extern "C" __global__ void __launch_bounds__(THREADS, 1)
snn_kernel(const float* __restrict__ xyz, float* __restrict__ out) {
    extern __shared__ unsigned char smem[];
    float*        vx     = (float*)smem;                      // 64 KB X
    float*        vy     = (float*)(smem + 65536);            // 64 KB Y
    float*        vz     = (float*)(smem + 131072);           // 64 KB Z
    const uint64_t* px   = (const uint64_t*)smem;             // pair views
    const uint64_t* py   = (const uint64_t*)(smem + 65536);
    const uint64_t* pz   = (const uint64_t*)(smem + 131072);
    unsigned int* used32 = (unsigned int*)(smem + 196608);    // 32 KB
    unsigned char* scr   = smem + 229376;                     // 3 KB
    uint64_t*     buf    = (uint64_t*)scr;                    // [128]
    unsigned int* hist   = (unsigned int*)(scr + 1024);       // [64]
    unsigned int* wcnt2  = (unsigned int*)(scr + 1280);       // [32]
    unsigned int* wmind  = (unsigned int*)(scr + 1408);       // [32]
    unsigned int* scnt2  = (unsigned int*)(scr + 1536);       // [2] parity
    unsigned int* sminu  = (unsigned int*)(scr + 1544);
    unsigned int* scen   = (unsigned int*)(scr + 1548);

    const int tid  = threadIdx.x;
    const int b    = blockIdx.x;
    const int lane = tid & 31;
    const int wid  = tid >> 5;

    // ---- init: SoA stage, zero used, RNG bits, phase-A state ----
    const float* g = xyz + (size_t)b * NPTS * 3;
    for (int i = tid; i < NPTS; i += THREADS) {
        vx[i] = g[3*i + 0];
        vy[i] = g[3*i + 1];
        vz[i] = g[3*i + 2];
    }
    for (int i = tid; i < NPTS / 2; i += THREADS) used32[i] = 0u;
    if (tid < 64) hist[tid] = (tid == 0) ? (unsigned)NPTS : 0u;
    if (tid < 32) wcnt2[tid] = NPTS / NWARP;                 // 512 each
    if (tid == 0) { scnt2[0] = 0u; scnt2[1] = 0u; *sminu = 0u; }

    {
        uint32_t bk0, bk1;
        tf2x32(0u, 42u, 0u, (uint32_t)b, bk0, bk1);          // batch key
        for (int q = tid; q < NQ; q += THREADS) {
            uint32_t qk0, qk1, a0, a1, e0, e1, x, y, hb, lb;
            tf2x32(bk0, bk1, 0u, (uint32_t)q, qk0, qk1);     // per-step key
            tf2x32(qk0, qk1, 0u, 0u, a0, a1);                // split[0]
            tf2x32(qk0, qk1, 0u, 1u, e0, e1);                // split[1]
            tf2x32(a0, a1, 0u, 0u, x, y);  hb = x ^ y;
            tf2x32(e0, e1, 0u, 0u, x, y);  lb = x ^ y;
            g_hb64[b*NQ + q] = ((uint64_t)hb << 32) | lb;
        }
    }
    __syncthreads();

    const size_t OUT_PTS = (size_t)BATCH * NQ * KNN;
    uint64_t hb64 = g_hb64[b * NQ];                          // prefetch q=0

    for (int q = 0; q < NQ; ++q) {
        const int gq = b * NQ + q;

        // ================= Phase A (incremental) =================
        uint32_t minU = *sminu;
        uint32_t cnt  = hist[minU];
        if (cnt == 0u) {                                     // rare: ~30 total
            // new minU in (minU, minU+32]: gap <= 29 since min <= mean <= 29
            uint32_t h = hist[minU + 1u + (uint32_t)lane];
            uint32_t mask = __ballot_sync(FULLM, h != 0u);
            uint32_t nm = minU + (uint32_t)__ffs(mask);
            uint32_t mm2 = nm * 0x10001u;
            uint32_t vc = 0u;
            #pragma unroll
            for (int k = 0; k < 8; ++k)
                vc += __vseteq2(used32[usw((uint32_t)tid * 8u + (uint32_t)k)], mm2);
            uint32_t cc = (vc & 0xFFFFu) + (vc >> 16);
            cc = __reduce_add_sync(FULLM, cc);
            if (lane == 0) wcnt2[wid] = cc;
            if (tid == 0) *sminu = nm;
            __syncthreads();                                 // rare bar
            minU = nm;
            cnt = hist[minU];
        }

        // randint via exact Barrett mods: ((hb%s)*((65536%s)^2%s)+lb%s)%s
        uint32_t rr;
        {
            uint32_t sp = cnt;
            uint32_t m = 0xFFFFFFFFu / sp;                   // Barrett factor
            uint32_t hbv = (uint32_t)(hb64 >> 32);
            uint32_t lbv = (uint32_t)hb64;
            uint32_t t65 = umodb(65536u, sp, m);
            uint32_t mlt = umodb(t65 * t65, sp, m);          // t65^2 < 2^28
            uint32_t am  = umodb(hbv, sp, m);
            uint32_t bm  = umodb(lbv, sp, m);
            rr = umodb(am * mlt + bm, sp, m);                // < 2^28 + 2^14
        }

        // owner warp from cached per-warp candidate counts
        uint32_t wv = wcnt2[lane];
        uint32_t sc = wv;
        #pragma unroll
        for (int o = 1; o < 32; o <<= 1) {
            uint32_t v = __shfl_up_sync(FULLM, sc, o);
            if (lane >= o) sc += v;
        }
        uint32_t myCnt = __shfl_sync(FULLM, wv, wid);
        uint32_t myPre = __shfl_sync(FULLM, sc, wid) - myCnt;

        if (rr >= myPre && rr < myPre + myCnt) {             // owner warp only
            uint32_t mm2 = minU * 0x10001u;
            uint32_t pw[8];
            uint32_t vc = 0u;
            #pragma unroll
            for (int k = 0; k < 8; ++k) {
                pw[k] = used32[usw((uint32_t)tid * 8u + (uint32_t)k)];
                vc += __vseteq2(pw[k], mm2);
            }
            uint32_t mi = (vc & 0xFFFFu) + (vc >> 16);
            uint32_t li = mi;
            #pragma unroll
            for (int o = 1; o < 32; o <<= 1) {
                uint32_t v = __shfl_up_sync(FULLM, li, o);
                if (lane >= o) li += v;
            }
            uint32_t need = rr - myPre;
            uint32_t le = li - mi;                           // exclusive
            if (need >= le && need < le + mi) {              // winner lane
                uint32_t nd = need - le;
                uint32_t c = 0; bool done = false;
                #pragma unroll
                for (int k = 0; k < 8; ++k) {
                    if (!done && (pw[k] & 0xFFFFu) == minU) {
                        if (nd == 0) { c = (uint32_t)tid*16u + 2u*k; done = true; }
                        else nd--;
                    }
                    if (!done && (pw[k] >> 16) == minU) {
                        if (nd == 0) { c = (uint32_t)tid*16u + 2u*k + 1u; done = true; }
                        else nd--;
                    }
                }
                *scen = c;
                size_t pofs = OUT_PTS + (size_t)gq * 3;
                out[pofs + 0] = vx[c];
                out[pofs + 1] = vy[c];
                out[pofs + 2] = vz[c];
            }
        }
        __syncthreads();                                     // bar1

        // ================= Phase B: packed distances =================
        const uint32_t c = *scen;
        if (tid == 0) scnt2[(q + 1) & 1] = 0u;               // reset next parity
        float cx = vx[c], cy = vy[c], cz = vz[c];
        uint64_t ncx, ncy, ncz;
        {
            float nx = -cx, ny = -cy, nz = -cz;
            asm("mov.b64 %0, {%1, %1};" : "=l"(ncx) : "f"(nx));
            asm("mov.b64 %0, {%1, %1};" : "=l"(ncy) : "f"(ny));
            asm("mov.b64 %0, {%1, %1};" : "=l"(ncz) : "f"(nz));
        }

        uint32_t db[16];
        #pragma unroll
        for (int jp = 0; jp < 8; ++jp) {
            int p = tid + (jp << 10);                        // pair index
            dist2pair(px[p], py[p], pz[p], ncx, ncy, ncz,
                      db[2*jp], db[2*jp + 1]);
        }
        uint32_t tm = db[0];
        #pragma unroll
        for (int j = 1; j < 16; ++j) tm = min(tm, db[j]);
        tm = __reduce_min_sync(FULLM, tm);
        if (lane == 0) wmind[wid] = tm;

        uint64_t hb64n = g_hb64[gq + 1];                     // prefetch next
        __syncthreads();                                     // bar2

        // ====== Phase C: T = max of 16 pair-minima; compaction ==========
        // pm = min(wmind[i], wmind[i+16]) is an element from disjoint warp
        // domains -> 16 distinct elements <= T -> top-16 subset of {d<=T}.
        uint32_t T;
        {
            uint32_t wl = wmind[lane];
            uint32_t pm = min(wl, __shfl_xor_sync(FULLM, wl, 16));
            T = __reduce_max_sync(FULLM, pm);
        }
        unsigned int* cur = &scnt2[q & 1];
        #pragma unroll
        for (int j = 0; j < 16; ++j) {
            if (db[j] <= T) {
                uint32_t s = atomicAdd(cur, 1u);
                if (s < CAP)
                    buf[s] = ((uint64_t)db[j] << 32) | didx((uint32_t)tid, j);
            }
        }
        __syncthreads();                                     // bar3

        // ====== Phase D: parallel rank -> winners; counter updates ==========
        const uint32_t C = scnt2[q & 1];                     // block-uniform
        if (C <= CAP) {
            if ((uint32_t)tid < C) {
                uint64_t my = buf[tid];
                uint32_t rank = 0;
                int j = 0;
                for (; j + 4 <= (int)C; j += 4) {
                    rank += (uint32_t)(buf[j]     < my);
                    rank += (uint32_t)(buf[j + 1] < my);
                    rank += (uint32_t)(buf[j + 2] < my);
                    rank += (uint32_t)(buf[j + 3] < my);
                }
                for (; j < (int)C; ++j) rank += (uint32_t)(buf[j] < my);
                if (rank < KNN) {
                    uint32_t myIdx = (uint32_t)my;
                    out[(size_t)gq * KNN + rank] = (float)myIdx;
                    bump1(myIdx, minU, used32, hist, wcnt2);
                }
            }
            if (tid == THREADS - 1)
                bump100(c, minU, used32, hist, wcnt2);
        } else {
            // ===== exact fallback (~5e-3/step): per-warp pop-16 via gmem ====
            uint32_t m1 = FULLM, m2 = FULLM, m3 = FULLM;
            uint32_t j1 = 0, j2 = 0, j3 = 0;
            #pragma unroll
            for (int j = 0; j < 16; ++j) {
                uint32_t v = db[j];
                if (v < m1)      { m3=m2; j3=j2; m2=m1; j2=j1; m1=v; j1=(uint32_t)j; }
                else if (v < m2) { m3=m2; j3=j2; m2=v; j2=(uint32_t)j; }
                else if (v < m3) { m3=v; j3=(uint32_t)j; }
            }
            uint32_t popped = 0;
            #pragma unroll 1
            for (int it = 0; it < KNN; ++it) {
                uint32_t wmin = __reduce_min_sync(FULLM, m1);
                uint32_t cand = (m1 == wmin) ? didx((uint32_t)tid, (int)j1) : FULLM;
                uint32_t imin = __reduce_min_sync(FULLM, cand);
                if (cand == imin) {
                    popped |= 1u << j1;
                    if (m2 != FULLM) { m1=m2; j1=j2; m2=m3; j2=j3; m3=FULLM; }
                    else {
                        m1 = m2 = m3 = FULLM; j1 = j2 = j3 = 0;
                        #pragma unroll
                        for (int j = 0; j < 16; ++j) {
                            uint32_t v = ((popped >> j) & 1u) ? FULLM : db[j];
                            if (v < m1)      { m3=m2; j3=j2; m2=m1; j2=j1; m1=v; j1=(uint32_t)j; }
                            else if (v < m2) { m3=m2; j3=j2; m2=v; j2=(uint32_t)j; }
                            else if (v < m3) { m3=v; j3=(uint32_t)j; }
                        }
                    }
                }
                if (lane == 0)
                    g_fb[(b * NWARP + wid) * KNN + it] =
                        ((unsigned long long)wmin << 32) | imin;
            }
            __syncthreads();     // uniform branch; orders g_fb for warp 0
            if (wid == 0) {
                int pos = 0;
                uint64_t head = g_fb[(b * NWARP + lane) * KNN];
                uint32_t myIdx = 0;
                #pragma unroll 1
                for (int it = 0; it < KNN; ++it) {
                    uint32_t hD = (uint32_t)(head >> 32);
                    uint32_t wmin = __reduce_min_sync(FULLM, hD);
                    uint32_t cand = (hD == wmin) ? (uint32_t)head : FULLM;
                    uint32_t imin = __reduce_min_sync(FULLM, cand);
                    if (cand == imin) {
                        pos++;
                        head = (pos < KNN)
                             ? g_fb[(b * NWARP + lane) * KNN + pos] : ~0ull;
                    }
                    if (lane == it) myIdx = imin;
                }
                if (lane < KNN) {
                    out[(size_t)gq * KNN + lane] = (float)myIdx;
                    bump1(myIdx, minU, used32, hist, wcnt2);
                }
                if (lane == KNN)
                    bump100(c, minU, used32, hist, wcnt2);
            }
        }
        __syncthreads();                                     // bar4
        hb64 = hb64n;
    }
}

extern "C" void kernel_launch(void* const* d_in, const int* in_sizes, int n_in,
                              void* d_out, int out_size) {
    (void)in_sizes; (void)n_in; (void)out_size;
    cudaFuncSetAttribute(snn_kernel,
                         cudaFuncAttributeMaxDynamicSharedMemorySize, SMEM_BYTES);
    snn_kernel<<<BATCH, THREADS, SMEM_BYTES>>>((const float*)d_in[0], (float*)d_out);
}

// round 14
// speedup vs baseline: 1.2729x; 1.0567x over previous
#include <cuda_runtime.h>
#include <cstdint>

// ============================================================================
// SampleNearestNeighborsLayer — exact JAX-semantics replay (bit-exact).
// Per batch b: 4096 sequential steps:
//   minU=min(used); cnt=#(used==minU); r=jax.random.randint(key_q,(),0,cnt)
//   center = r-th least-used point (index order); d_i = ||xyz_i - xyz_c||^2
//   ids = 16 smallest (d,i) lexicographic; used[ids]+=1; used[center]+=100
// Output (float32): idx (8*4096*16) then pts (8*4096*3).
//
// == Round-10 kernel (best: 14.07 ms) with ONE change: pair-packed loads ==
// (float4 xy-quad + float2 z-pair per point-pair: 2 LDS vs 3, +2 repacks).
// Phase A incremental (hist + per-warp candidate counts maintained by the 17
// atomic counter updates; full rescan only when hist[minU] empties, ~30x).
// Distances in packed f32x2 (two independent rn ops == scalar, bit-exact).
// Threshold T = max of 16 pair-minima: 16 distinct elements <= T certify
// top-16 in {d<=T}. Per-hit atomic compaction; per-thread parallel rank.
// C > CAP (P~5e-3/step) -> exact fallback.
// ============================================================================

#define NQ      4096
#define NPTS    16384
#define KNN     16
#define BATCH   8
#define THREADS 1024
#define NWARP   32
#define CAP     128
#define SMEM_BYTES 232448
#define FULLM   0xFFFFFFFFu

__device__ uint64_t g_hb64[BATCH * NQ + 8];               // +pad for prefetch
__device__ unsigned long long g_fb[BATCH * NWARP * KNN];  // fallback staging

__device__ __forceinline__ uint32_t rotl32(uint32_t x, int r) {
    return (x << r) | (x >> (32 - r));
}

// Threefry-2x32, 20 rounds (JAX schedule) — verified bit-exact on HW.
__device__ __forceinline__ void tf2x32(uint32_t k0, uint32_t k1,
                                       uint32_t x0, uint32_t x1,
                                       uint32_t& o0, uint32_t& o1) {
    uint32_t ks2 = k0 ^ k1 ^ 0x1BD11BDAu;
    x0 += k0; x1 += k1;
#define TFR(r) { x0 += x1; x1 = rotl32(x1, (r)); x1 ^= x0; }
    TFR(13) TFR(15) TFR(26) TFR(6)
    x0 += k1;  x1 += ks2 + 1u;
    TFR(17) TFR(29) TFR(16) TFR(24)
    x0 += ks2; x1 += k0 + 2u;
    TFR(13) TFR(15) TFR(26) TFR(6)
    x0 += k0;  x1 += k1 + 3u;
    TFR(17) TFR(29) TFR(16) TFR(24)
    x0 += k1;  x1 += ks2 + 4u;
    TFR(13) TFR(15) TFR(26) TFR(6)
    x0 += ks2; x1 += k0 + 5u;
#undef TFR
    o0 = x0; o1 = x1;
}

// used[] as u16 pairs in u32 words; word W stored at usw(W) — conflict-free
// for the per-thread contiguous 8-word scan.
__device__ __forceinline__ uint32_t usw(uint32_t W) { return W ^ ((W >> 5) & 31u); }

// Packed pair distance: d = ((dx*dx + dy*dy) + dz*dz) per lane of the f32x2,
// dx = x + (-cx) (IEEE-identical to __fsub_rn). Each f32x2 op is two
// independent round-to-nearest f32 ops -> bit-exact vs scalar.
__device__ __forceinline__ void dist2pair(uint64_t xx, uint64_t yy, uint64_t zz,
                                          uint64_t ncx, uint64_t ncy, uint64_t ncz,
                                          uint32_t& lo, uint32_t& hi) {
    uint64_t dx, dy, dz, sx, sy, szv, t, d;
    asm("add.rn.f32x2 %0, %1, %2;" : "=l"(dx) : "l"(xx), "l"(ncx));
    asm("add.rn.f32x2 %0, %1, %2;" : "=l"(dy) : "l"(yy), "l"(ncy));
    asm("add.rn.f32x2 %0, %1, %2;" : "=l"(dz) : "l"(zz), "l"(ncz));
    asm("mul.rn.f32x2 %0, %1, %2;" : "=l"(sx) : "l"(dx), "l"(dx));
    asm("mul.rn.f32x2 %0, %1, %2;" : "=l"(sy) : "l"(dy), "l"(dy));
    asm("mul.rn.f32x2 %0, %1, %2;" : "=l"(szv) : "l"(dz), "l"(dz));
    asm("add.rn.f32x2 %0, %1, %2;" : "=l"(t) : "l"(sx), "l"(sy));
    asm("add.rn.f32x2 %0, %1, %2;" : "=l"(d) : "l"(t), "l"(szv));
    asm("mov.b64 {%0, %1}, %2;" : "=r"(lo), "=r"(hi) : "l"(d));
}

// Point index for db[j]: pair p = tid + 1024*(j>>1), point = 2p + (j&1).
__device__ __forceinline__ uint32_t didx(uint32_t tid, int j) {
    return 2u * tid + (((uint32_t)j >> 1) << 11) + ((uint32_t)j & 1u);
}

// used[idx] += 1 with exact hist/wcnt2 bookkeeping (transition counted once
// via the atomic's returned old value; values < 4300 << 65536, no carry).
__device__ __forceinline__ void bump1(uint32_t idx, uint32_t minU,
                                      unsigned int* used32,
                                      unsigned int* hist,
                                      unsigned int* wcnt2) {
    uint32_t sh = (idx & 1u) * 16u;
    uint32_t oldw = atomicAdd(&used32[usw(idx >> 1)], 1u << sh);
    uint32_t ov = (oldw >> sh) & 0xFFFFu;
    if (ov < 64u)      atomicSub(&hist[ov], 1u);
    if (ov + 1u < 64u) atomicAdd(&hist[ov + 1u], 1u);
    if (ov == minU)    atomicSub(&wcnt2[idx >> 9], 1u);
}

__device__ __forceinline__ void bump100(uint32_t idx, uint32_t minU,
                                        unsigned int* used32,
                                        unsigned int* hist,
                                        unsigned int* wcnt2) {
    uint32_t sh = (idx & 1u) * 16u;
    uint32_t oldw = atomicAdd(&used32[usw(idx >> 1)], 100u << sh);
    uint32_t ov = (oldw >> sh) & 0xFFFFu;
    if (ov < 64u)   atomicSub(&hist[ov], 1u);   // ov+100 >= 64 always
    if (ov == minU) atomicSub(&wcnt2[idx >> 9], 1u);
}

extern "C" __global__ void __launch_bounds__(THREADS, 1)
snn_kernel(const float* __restrict__ xyz, float* __restrict__ out) {
    extern __shared__ unsigned char smem[];
    float4*       sp4    = (float4*)smem;                     // 128 KB xy quads
    float2*       sz2    = (float2*)(smem + 131072);          // 64 KB z pairs
    const uint64_t* pz   = (const uint64_t*)(smem + 131072);  // z-pair u64 view
    unsigned int* used32 = (unsigned int*)(smem + 196608);    // 32 KB
    unsigned char* scr   = smem + 229376;                     // 3 KB
    uint64_t*     buf    = (uint64_t*)scr;                    // [128]
    unsigned int* hist   = (unsigned int*)(scr + 1024);       // [64]
    unsigned int* wcnt2  = (unsigned int*)(scr + 1280);       // [32]
    unsigned int* wmind  = (unsigned int*)(scr + 1408);       // [32]
    unsigned int* scnt2  = (unsigned int*)(scr + 1536);       // [2] parity
    unsigned int* sminu  = (unsigned int*)(scr + 1544);
    unsigned int* scen   = (unsigned int*)(scr + 1548);

    const int tid  = threadIdx.x;
    const int b    = blockIdx.x;
    const int lane = tid & 31;
    const int wid  = tid >> 5;

    // ---- init: pairwise stage, zero used, RNG bits, phase-A state ----
    const float* g = xyz + (size_t)b * NPTS * 3;
    for (int i = tid; i < NPTS / 2; i += THREADS) {
        const float* p0 = g + 6 * i;
        sp4[i] = make_float4(p0[0], p0[1], p0[3], p0[4]);
        sz2[i] = make_float2(p0[2], p0[5]);
    }
    for (int i = tid; i < NPTS / 2; i += THREADS) used32[i] = 0u;
    if (tid < 64) hist[tid] = (tid == 0) ? (unsigned)NPTS : 0u;
    if (tid < 32) wcnt2[tid] = NPTS / NWARP;                 // 512 each
    if (tid == 0) { scnt2[0] = 0u; scnt2[1] = 0u; *sminu = 0u; }

    {
        uint32_t bk0, bk1;
        tf2x32(0u, 42u, 0u, (uint32_t)b, bk0, bk1);          // batch key
        for (int q = tid; q < NQ; q += THREADS) {
            uint32_t qk0, qk1, a0, a1, e0, e1, x, y, hb, lb;
            tf2x32(bk0, bk1, 0u, (uint32_t)q, qk0, qk1);     // per-step key
            tf2x32(qk0, qk1, 0u, 0u, a0, a1);                // split[0]
            tf2x32(qk0, qk1, 0u, 1u, e0, e1);                // split[1]
            tf2x32(a0, a1, 0u, 0u, x, y);  hb = x ^ y;
            tf2x32(e0, e1, 0u, 0u, x, y);  lb = x ^ y;
            g_hb64[b*NQ + q] = ((uint64_t)hb << 32) | lb;
        }
    }
    __syncthreads();

    const size_t OUT_PTS = (size_t)BATCH * NQ * KNN;
    uint64_t hb64 = g_hb64[b * NQ];                          // prefetch q=0

    for (int q = 0; q < NQ; ++q) {
        const int gq = b * NQ + q;

        // ================= Phase A (incremental) =================
        uint32_t minU = *sminu;
        uint32_t cnt  = hist[minU];
        if (cnt == 0u) {                                     // rare: ~30 total
            // new minU in (minU, minU+32]: gap <= 29 since min <= mean <= 29
            uint32_t h = hist[minU + 1u + (uint32_t)lane];
            uint32_t mask = __ballot_sync(FULLM, h != 0u);
            uint32_t nm = minU + (uint32_t)__ffs(mask);
            uint32_t mm2 = nm * 0x10001u;
            uint32_t vc = 0u;
            #pragma unroll
            for (int k = 0; k < 8; ++k)
                vc += __vseteq2(used32[usw((uint32_t)tid * 8u + (uint32_t)k)], mm2);
            uint32_t cc = (vc & 0xFFFFu) + (vc >> 16);
            cc = __reduce_add_sync(FULLM, cc);
            if (lane == 0) wcnt2[wid] = cc;
            if (tid == 0) *sminu = nm;
            __syncthreads();                                 // rare bar
            minU = nm;
            cnt = hist[minU];
        }

        // randint (all u32, verified): ((hb%s)*((65536%s)^2%s)+lb%s)%s
        uint32_t rr;
        {
            uint32_t sp = cnt;
            uint32_t hbv = (uint32_t)(hb64 >> 32);
            uint32_t lbv = (uint32_t)hb64;
            uint32_t mlt = 65536u % sp;
            mlt = (mlt * mlt) % sp;
            rr = ((hbv % sp) * mlt + (lbv % sp)) % sp;
        }

        // owner warp from cached per-warp candidate counts
        uint32_t wv = wcnt2[lane];
        uint32_t sc = wv;
        #pragma unroll
        for (int o = 1; o < 32; o <<= 1) {
            uint32_t v = __shfl_up_sync(FULLM, sc, o);
            if (lane >= o) sc += v;
        }
        uint32_t myCnt = __shfl_sync(FULLM, wv, wid);
        uint32_t myPre = __shfl_sync(FULLM, sc, wid) - myCnt;

        if (rr >= myPre && rr < myPre + myCnt) {             // owner warp only
            uint32_t mm2 = minU * 0x10001u;
            uint32_t pw[8];
            uint32_t vc = 0u;
            #pragma unroll
            for (int k = 0; k < 8; ++k) {
                pw[k] = used32[usw((uint32_t)tid * 8u + (uint32_t)k)];
                vc += __vseteq2(pw[k], mm2);
            }
            uint32_t mi = (vc & 0xFFFFu) + (vc >> 16);
            uint32_t li = mi;
            #pragma unroll
            for (int o = 1; o < 32; o <<= 1) {
                uint32_t v = __shfl_up_sync(FULLM, li, o);
                if (lane >= o) li += v;
            }
            uint32_t need = rr - myPre;
            uint32_t le = li - mi;                           // exclusive
            if (need >= le && need < le + mi) {              // winner lane
                uint32_t nd = need - le;
                uint32_t c = 0; bool done = false;
                #pragma unroll
                for (int k = 0; k < 8; ++k) {
                    if (!done && (pw[k] & 0xFFFFu) == minU) {
                        if (nd == 0) { c = (uint32_t)tid*16u + 2u*k; done = true; }
                        else nd--;
                    }
                    if (!done && (pw[k] >> 16) == minU) {
                        if (nd == 0) { c = (uint32_t)tid*16u + 2u*k + 1u; done = true; }
                        else nd--;
                    }
                }
                *scen = c;
                size_t pofs = OUT_PTS + (size_t)gq * 3;
                float4 wc = sp4[c >> 1];
                float2 zc = sz2[c >> 1];
                out[pofs + 0] = (c & 1u) ? wc.z : wc.x;
                out[pofs + 1] = (c & 1u) ? wc.w : wc.y;
                out[pofs + 2] = (c & 1u) ? zc.y : zc.x;
            }
        }
        __syncthreads();                                     // bar1

        // ================= Phase B: packed distances (pair loads) ===========
        const uint32_t c = *scen;
        if (tid == 0) scnt2[(q + 1) & 1] = 0u;               // reset next parity
        float4 wc = sp4[c >> 1];
        float2 zc = sz2[c >> 1];
        const float cx = (c & 1u) ? wc.z : wc.x;
        const float cy = (c & 1u) ? wc.w : wc.y;
        const float cz = (c & 1u) ? zc.y : zc.x;
        uint64_t ncx, ncy, ncz;
        {
            float nx = -cx, ny = -cy, nz = -cz;
            asm("mov.b64 %0, {%1, %1};" : "=l"(ncx) : "f"(nx));
            asm("mov.b64 %0, {%1, %1};" : "=l"(ncy) : "f"(ny));
            asm("mov.b64 %0, {%1, %1};" : "=l"(ncz) : "f"(nz));
        }

        uint32_t db[16];
        #pragma unroll
        for (int jp = 0; jp < 8; ++jp) {
            int p = tid + (jp << 10);                        // pair index
            float4 w = sp4[p];                               // LDS.128
            uint64_t zz = pz[p];                             // LDS.64 (z pair)
            uint64_t xx, yy;
            asm("mov.b64 %0, {%1, %2};" : "=l"(xx) : "f"(w.x), "f"(w.z));
            asm("mov.b64 %0, {%1, %2};" : "=l"(yy) : "f"(w.y), "f"(w.w));
            dist2pair(xx, yy, zz, ncx, ncy, ncz, db[2*jp], db[2*jp + 1]);
        }
        uint32_t tm = db[0];
        #pragma unroll
        for (int j = 1; j < 16; ++j) tm = min(tm, db[j]);
        tm = __reduce_min_sync(FULLM, tm);
        if (lane == 0) wmind[wid] = tm;

        uint64_t hb64n = g_hb64[gq + 1];                     // prefetch next
        __syncthreads();                                     // bar2

        // ====== Phase C: T = max of 16 pair-minima; compaction ==========
        // pm = min(wmind[i], wmind[i+16]) is an element from disjoint warp
        // domains -> 16 distinct elements <= T -> top-16 subset of {d<=T}.
        uint32_t T;
        {
            uint32_t wl = wmind[lane];
            uint32_t pm = min(wl, __shfl_xor_sync(FULLM, wl, 16));
            T = __reduce_max_sync(FULLM, pm);
        }
        unsigned int* cur = &scnt2[q & 1];
        #pragma unroll
        for (int j = 0; j < 16; ++j) {
            if (db[j] <= T) {
                uint32_t s = atomicAdd(cur, 1u);
                if (s < CAP)
                    buf[s] = ((uint64_t)db[j] << 32) | didx((uint32_t)tid, j);
            }
        }
        __syncthreads();                                     // bar3

        // ====== Phase D: parallel rank -> winners; counter updates ==========
        const uint32_t C = scnt2[q & 1];                     // block-uniform
        if (C <= CAP) {
            if ((uint32_t)tid < C) {
                uint64_t my = buf[tid];
                uint32_t rank = 0;
                int j = 0;
                for (; j + 4 <= (int)C; j += 4) {
                    rank += (uint32_t)(buf[j]     < my);
                    rank += (uint32_t)(buf[j + 1] < my);
                    rank += (uint32_t)(buf[j + 2] < my);
                    rank += (uint32_t)(buf[j + 3] < my);
                }
                for (; j < (int)C; ++j) rank += (uint32_t)(buf[j] < my);
                if (rank < KNN) {
                    uint32_t myIdx = (uint32_t)my;
                    out[(size_t)gq * KNN + rank] = (float)myIdx;
                    bump1(myIdx, minU, used32, hist, wcnt2);
                }
            }
            if (tid == THREADS - 1)
                bump100(c, minU, used32, hist, wcnt2);
        } else {
            // ===== exact fallback (~5e-3/step): per-warp pop-16 via gmem ====
            uint32_t m1 = FULLM, m2 = FULLM, m3 = FULLM;
            uint32_t j1 = 0, j2 = 0, j3 = 0;
            #pragma unroll
            for (int j = 0; j < 16; ++j) {
                uint32_t v = db[j];
                if (v < m1)      { m3=m2; j3=j2; m2=m1; j2=j1; m1=v; j1=(uint32_t)j; }
                else if (v < m2) { m3=m2; j3=j2; m2=v; j2=(uint32_t)j; }
                else if (v < m3) { m3=v; j3=(uint32_t)j; }
            }
            uint32_t popped = 0;
            #pragma unroll 1
            for (int it = 0; it < KNN; ++it) {
                uint32_t wmin = __reduce_min_sync(FULLM, m1);
                uint32_t cand = (m1 == wmin) ? didx((uint32_t)tid, (int)j1) : FULLM;
                uint32_t imin = __reduce_min_sync(FULLM, cand);
                if (cand == imin) {
                    popped |= 1u << j1;
                    if (m2 != FULLM) { m1=m2; j1=j2; m2=m3; j2=j3; m3=FULLM; }
                    else {
                        m1 = m2 = m3 = FULLM; j1 = j2 = j3 = 0;
                        #pragma unroll
                        for (int j = 0; j < 16; ++j) {
                            uint32_t v = ((popped >> j) & 1u) ? FULLM : db[j];
                            if (v < m1)      { m3=m2; j3=j2; m2=m1; j2=j1; m1=v; j1=(uint32_t)j; }
                            else if (v < m2) { m3=m2; j3=j2; m2=v; j2=(uint32_t)j; }
                            else if (v < m3) { m3=v; j3=(uint32_t)j; }
                        }
                    }
                }
                if (lane == 0)
                    g_fb[(b * NWARP + wid) * KNN + it] =
                        ((unsigned long long)wmin << 32) | imin;
            }
            __syncthreads();     // uniform branch; orders g_fb for warp 0
            if (wid == 0) {
                int pos = 0;
                uint64_t head = g_fb[(b * NWARP + lane) * KNN];
                uint32_t myIdx = 0;
                #pragma unroll 1
                for (int it = 0; it < KNN; ++it) {
                    uint32_t hD = (uint32_t)(head >> 32);
                    uint32_t wmin = __reduce_min_sync(FULLM, hD);
                    uint32_t cand = (hD == wmin) ? (uint32_t)head : FULLM;
                    uint32_t imin = __reduce_min_sync(FULLM, cand);
                    if (cand == imin) {
                        pos++;
                        head = (pos < KNN)
                             ? g_fb[(b * NWARP + lane) * KNN + pos] : ~0ull;
                    }
                    if (lane == it) myIdx = imin;
                }
                if (lane < KNN) {
                    out[(size_t)gq * KNN + lane] = (float)myIdx;
                    bump1(myIdx, minU, used32, hist, wcnt2);
                }
                if (lane == KNN)
                    bump100(c, minU, used32, hist, wcnt2);
            }
        }
        __syncthreads();                                     // bar4
        hb64 = hb64n;
    }
}

extern "C" void kernel_launch(void* const* d_in, const int* in_sizes, int n_in,
                              void* d_out, int out_size) {
    (void)in_sizes; (void)n_in; (void)out_size;
    cudaFuncSetAttribute(snn_kernel,
                         cudaFuncAttributeMaxDynamicSharedMemorySize, SMEM_BYTES);
    snn_kernel<<<BATCH, THREADS, SMEM_BYTES>>>((const float*)d_in[0], (float*)d_out);
}

// round 15
// speedup vs baseline: 1.3110x; 1.0299x over previous
#include <cuda_runtime.h>
#include <cstdint>

// ============================================================================
// SampleNearestNeighborsLayer — exact JAX-semantics replay (bit-exact).
// Per batch b: 4096 sequential steps:
//   minU=min(used); cnt=#(used==minU); r=jax.random.randint(key_q,(),0,cnt)
//   center = r-th least-used point (index order); d_i = ||xyz_i - xyz_c||^2
//   ids = 16 smallest (d,i) lexicographic; used[ids]+=1; used[center]+=100
// Output (float32): idx (8*4096*16) then pts (8*4096*3).
//
// == Round-10 base (best: 14.07 ms) + REDUX owner-prefix + LDS.128 rank. ==
// Phase A incremental (hist + per-warp candidate counts maintained by the 17
// atomic counter updates; full rescan only when hist[minU] empties, ~30x).
// Distances in packed f32x2 (two independent rn ops == scalar, bit-exact).
// Threshold T = max of 16 pair-minima: 16 distinct elements <= T certify
// top-16 in {d<=T}. Per-hit atomic compaction; per-thread parallel rank.
// C > CAP (P~5e-3/step) -> exact fallback.
// ============================================================================

#define NQ      4096
#define NPTS    16384
#define KNN     16
#define BATCH   8
#define THREADS 1024
#define NWARP   32
#define CAP     128
#define SMEM_BYTES 232448
#define FULLM   0xFFFFFFFFu

__device__ uint64_t g_hb64[BATCH * NQ + 8];               // +pad for prefetch
__device__ unsigned long long g_fb[BATCH * NWARP * KNN];  // fallback staging

__device__ __forceinline__ uint32_t rotl32(uint32_t x, int r) {
    return (x << r) | (x >> (32 - r));
}

// Threefry-2x32, 20 rounds (JAX schedule) — verified bit-exact on HW.
__device__ __forceinline__ void tf2x32(uint32_t k0, uint32_t k1,
                                       uint32_t x0, uint32_t x1,
                                       uint32_t& o0, uint32_t& o1) {
    uint32_t ks2 = k0 ^ k1 ^ 0x1BD11BDAu;
    x0 += k0; x1 += k1;
#define TFR(r) { x0 += x1; x1 = rotl32(x1, (r)); x1 ^= x0; }
    TFR(13) TFR(15) TFR(26) TFR(6)
    x0 += k1;  x1 += ks2 + 1u;
    TFR(17) TFR(29) TFR(16) TFR(24)
    x0 += ks2; x1 += k0 + 2u;
    TFR(13) TFR(15) TFR(26) TFR(6)
    x0 += k0;  x1 += k1 + 3u;
    TFR(17) TFR(29) TFR(16) TFR(24)
    x0 += k1;  x1 += ks2 + 4u;
    TFR(13) TFR(15) TFR(26) TFR(6)
    x0 += ks2; x1 += k0 + 5u;
#undef TFR
    o0 = x0; o1 = x1;
}

// used[] as u16 pairs in u32 words; word W stored at usw(W) — conflict-free
// for the per-thread contiguous 8-word scan.
__device__ __forceinline__ uint32_t usw(uint32_t W) { return W ^ ((W >> 5) & 31u); }

// Packed pair distance: d = ((dx*dx + dy*dy) + dz*dz) per lane of the f32x2,
// dx = x + (-cx) (IEEE-identical to __fsub_rn). Each f32x2 op is two
// independent round-to-nearest f32 ops -> bit-exact vs scalar.
__device__ __forceinline__ void dist2pair(uint64_t xx, uint64_t yy, uint64_t zz,
                                          uint64_t ncx, uint64_t ncy, uint64_t ncz,
                                          uint32_t& lo, uint32_t& hi) {
    uint64_t dx, dy, dz, sx, sy, szv, t, d;
    asm("add.rn.f32x2 %0, %1, %2;" : "=l"(dx) : "l"(xx), "l"(ncx));
    asm("add.rn.f32x2 %0, %1, %2;" : "=l"(dy) : "l"(yy), "l"(ncy));
    asm("add.rn.f32x2 %0, %1, %2;" : "=l"(dz) : "l"(zz), "l"(ncz));
    asm("mul.rn.f32x2 %0, %1, %2;" : "=l"(sx) : "l"(dx), "l"(dx));
    asm("mul.rn.f32x2 %0, %1, %2;" : "=l"(sy) : "l"(dy), "l"(dy));
    asm("mul.rn.f32x2 %0, %1, %2;" : "=l"(szv) : "l"(dz), "l"(dz));
    asm("add.rn.f32x2 %0, %1, %2;" : "=l"(t) : "l"(sx), "l"(sy));
    asm("add.rn.f32x2 %0, %1, %2;" : "=l"(d) : "l"(t), "l"(szv));
    asm("mov.b64 {%0, %1}, %2;" : "=r"(lo), "=r"(hi) : "l"(d));
}

// Point index for db[j]: pair p = tid + 1024*(j>>1), point = 2p + (j&1).
__device__ __forceinline__ uint32_t didx(uint32_t tid, int j) {
    return 2u * tid + (((uint32_t)j >> 1) << 11) + ((uint32_t)j & 1u);
}

// used[idx] += 1 with exact hist/wcnt2 bookkeeping (transition counted once
// via the atomic's returned old value; values < 4300 << 65536, no carry).
__device__ __forceinline__ void bump1(uint32_t idx, uint32_t minU,
                                      unsigned int* used32,
                                      unsigned int* hist,
                                      unsigned int* wcnt2) {
    uint32_t sh = (idx & 1u) * 16u;
    uint32_t oldw = atomicAdd(&used32[usw(idx >> 1)], 1u << sh);
    uint32_t ov = (oldw >> sh) & 0xFFFFu;
    if (ov < 64u)      atomicSub(&hist[ov], 1u);
    if (ov + 1u < 64u) atomicAdd(&hist[ov + 1u], 1u);
    if (ov == minU)    atomicSub(&wcnt2[idx >> 9], 1u);
}

__device__ __forceinline__ void bump100(uint32_t idx, uint32_t minU,
                                        unsigned int* used32,
                                        unsigned int* hist,
                                        unsigned int* wcnt2) {
    uint32_t sh = (idx & 1u) * 16u;
    uint32_t oldw = atomicAdd(&used32[usw(idx >> 1)], 100u << sh);
    uint32_t ov = (oldw >> sh) & 0xFFFFu;
    if (ov < 64u)   atomicSub(&hist[ov], 1u);   // ov+100 >= 64 always
    if (ov == minU) atomicSub(&wcnt2[idx >> 9], 1u);
}

extern "C" __global__ void __launch_bounds__(THREADS, 1)
snn_kernel(const float* __restrict__ xyz, float* __restrict__ out) {
    extern __shared__ unsigned char smem[];
    float*        vx     = (float*)smem;                      // 64 KB X
    float*        vy     = (float*)(smem + 65536);            // 64 KB Y
    float*        vz     = (float*)(smem + 131072);           // 64 KB Z
    const uint64_t* px   = (const uint64_t*)smem;             // pair views
    const uint64_t* py   = (const uint64_t*)(smem + 65536);
    const uint64_t* pz   = (const uint64_t*)(smem + 131072);
    unsigned int* used32 = (unsigned int*)(smem + 196608);    // 32 KB
    unsigned char* scr   = smem + 229376;                     // 3 KB
    uint64_t*     buf    = (uint64_t*)scr;                    // [128], 16B align
    unsigned int* hist   = (unsigned int*)(scr + 1024);       // [64]
    unsigned int* wcnt2  = (unsigned int*)(scr + 1280);       // [32]
    unsigned int* wmind  = (unsigned int*)(scr + 1408);       // [32]
    unsigned int* scnt2  = (unsigned int*)(scr + 1536);       // [2] parity
    unsigned int* sminu  = (unsigned int*)(scr + 1544);
    unsigned int* scen   = (unsigned int*)(scr + 1548);

    const int tid  = threadIdx.x;
    const int b    = blockIdx.x;
    const int lane = tid & 31;
    const int wid  = tid >> 5;

    // ---- init: SoA stage, zero used, RNG bits, phase-A state ----
    const float* g = xyz + (size_t)b * NPTS * 3;
    for (int i = tid; i < NPTS; i += THREADS) {
        vx[i] = g[3*i + 0];
        vy[i] = g[3*i + 1];
        vz[i] = g[3*i + 2];
    }
    for (int i = tid; i < NPTS / 2; i += THREADS) used32[i] = 0u;
    if (tid < 64) hist[tid] = (tid == 0) ? (unsigned)NPTS : 0u;
    if (tid < 32) wcnt2[tid] = NPTS / NWARP;                 // 512 each
    if (tid == 0) { scnt2[0] = 0u; scnt2[1] = 0u; *sminu = 0u; }

    {
        uint32_t bk0, bk1;
        tf2x32(0u, 42u, 0u, (uint32_t)b, bk0, bk1);          // batch key
        for (int q = tid; q < NQ; q += THREADS) {
            uint32_t qk0, qk1, a0, a1, e0, e1, x, y, hb, lb;
            tf2x32(bk0, bk1, 0u, (uint32_t)q, qk0, qk1);     // per-step key
            tf2x32(qk0, qk1, 0u, 0u, a0, a1);                // split[0]
            tf2x32(qk0, qk1, 0u, 1u, e0, e1);                // split[1]
            tf2x32(a0, a1, 0u, 0u, x, y);  hb = x ^ y;
            tf2x32(e0, e1, 0u, 0u, x, y);  lb = x ^ y;
            g_hb64[b*NQ + q] = ((uint64_t)hb << 32) | lb;
        }
    }
    __syncthreads();

    const size_t OUT_PTS = (size_t)BATCH * NQ * KNN;
    uint64_t hb64 = g_hb64[b * NQ];                          // prefetch q=0

    for (int q = 0; q < NQ; ++q) {
        const int gq = b * NQ + q;

        // ================= Phase A (incremental) =================
        uint32_t minU = *sminu;
        uint32_t cnt  = hist[minU];
        if (cnt == 0u) {                                     // rare: ~30 total
            // new minU in (minU, minU+32]: gap <= 29 since min <= mean <= 29
            uint32_t h = hist[minU + 1u + (uint32_t)lane];
            uint32_t mask = __ballot_sync(FULLM, h != 0u);
            uint32_t nm = minU + (uint32_t)__ffs(mask);
            uint32_t mm2 = nm * 0x10001u;
            uint32_t vc = 0u;
            #pragma unroll
            for (int k = 0; k < 8; ++k)
                vc += __vseteq2(used32[usw((uint32_t)tid * 8u + (uint32_t)k)], mm2);
            uint32_t cc = (vc & 0xFFFFu) + (vc >> 16);
            cc = __reduce_add_sync(FULLM, cc);
            if (lane == 0) wcnt2[wid] = cc;
            if (tid == 0) *sminu = nm;
            __syncthreads();                                 // rare bar
            minU = nm;
            cnt = hist[minU];
        }

        // randint (all u32, verified): ((hb%s)*((65536%s)^2%s)+lb%s)%s
        uint32_t rr;
        {
            uint32_t sp = cnt;
            uint32_t hbv = (uint32_t)(hb64 >> 32);
            uint32_t lbv = (uint32_t)hb64;
            uint32_t mlt = 65536u % sp;
            mlt = (mlt * mlt) % sp;
            rr = ((hbv % sp) * mlt + (lbv % sp)) % sp;
        }

        // owner warp: exclusive prefix over wcnt2 via single REDUX
        uint32_t wv = wcnt2[lane];
        uint32_t myPre = __reduce_add_sync(FULLM, (lane < wid) ? wv : 0u);
        uint32_t myCnt = __shfl_sync(FULLM, wv, wid);

        if (rr >= myPre && rr < myPre + myCnt) {             // owner warp only
            uint32_t mm2 = minU * 0x10001u;
            uint32_t pw[8];
            uint32_t vc = 0u;
            #pragma unroll
            for (int k = 0; k < 8; ++k) {
                pw[k] = used32[usw((uint32_t)tid * 8u + (uint32_t)k)];
                vc += __vseteq2(pw[k], mm2);
            }
            uint32_t mi = (vc & 0xFFFFu) + (vc >> 16);
            uint32_t li = mi;
            #pragma unroll
            for (int o = 1; o < 32; o <<= 1) {
                uint32_t v = __shfl_up_sync(FULLM, li, o);
                if (lane >= o) li += v;
            }
            uint32_t need = rr - myPre;
            uint32_t le = li - mi;                           // exclusive
            if (need >= le && need < le + mi) {              // winner lane
                uint32_t nd = need - le;
                uint32_t c = 0; bool done = false;
                #pragma unroll
                for (int k = 0; k < 8; ++k) {
                    if (!done && (pw[k] & 0xFFFFu) == minU) {
                        if (nd == 0) { c = (uint32_t)tid*16u + 2u*k; done = true; }
                        else nd--;
                    }
                    if (!done && (pw[k] >> 16) == minU) {
                        if (nd == 0) { c = (uint32_t)tid*16u + 2u*k + 1u; done = true; }
                        else nd--;
                    }
                }
                *scen = c;
                size_t pofs = OUT_PTS + (size_t)gq * 3;
                out[pofs + 0] = vx[c];
                out[pofs + 1] = vy[c];
                out[pofs + 2] = vz[c];
            }
        }
        __syncthreads();                                     // bar1

        // ================= Phase B: packed distances =================
        const uint32_t c = *scen;
        if (tid == 0) scnt2[(q + 1) & 1] = 0u;               // reset next parity
        float cx = vx[c], cy = vy[c], cz = vz[c];
        uint64_t ncx, ncy, ncz;
        {
            float nx = -cx, ny = -cy, nz = -cz;
            asm("mov.b64 %0, {%1, %1};" : "=l"(ncx) : "f"(nx));
            asm("mov.b64 %0, {%1, %1};" : "=l"(ncy) : "f"(ny));
            asm("mov.b64 %0, {%1, %1};" : "=l"(ncz) : "f"(nz));
        }

        uint32_t db[16];
        #pragma unroll
        for (int jp = 0; jp < 8; ++jp) {
            int p = tid + (jp << 10);                        // pair index
            dist2pair(px[p], py[p], pz[p], ncx, ncy, ncz,
                      db[2*jp], db[2*jp + 1]);
        }
        uint32_t tm = db[0];
        #pragma unroll
        for (int j = 1; j < 16; ++j) tm = min(tm, db[j]);
        tm = __reduce_min_sync(FULLM, tm);
        if (lane == 0) wmind[wid] = tm;

        uint64_t hb64n = g_hb64[gq + 1];                     // prefetch next
        __syncthreads();                                     // bar2

        // ====== Phase C: T = max of 16 pair-minima; compaction ==========
        // pm = min(wmind[i], wmind[i+16]) is an element from disjoint warp
        // domains -> 16 distinct elements <= T -> top-16 subset of {d<=T}.
        uint32_t T;
        {
            uint32_t wl = wmind[lane];
            uint32_t pm = min(wl, __shfl_xor_sync(FULLM, wl, 16));
            T = __reduce_max_sync(FULLM, pm);
        }
        unsigned int* cur = &scnt2[q & 1];
        #pragma unroll
        for (int j = 0; j < 16; ++j) {
            if (db[j] <= T) {
                uint32_t s = atomicAdd(cur, 1u);
                if (s < CAP)
                    buf[s] = ((uint64_t)db[j] << 32) | didx((uint32_t)tid, j);
            }
        }
        __syncthreads();                                     // bar3

        // ====== Phase D: parallel rank (LDS.128 pairs) ==========
        const uint32_t C = scnt2[q & 1];                     // block-uniform
        if (C <= CAP) {
            if ((uint32_t)tid < C) {
                uint64_t my = buf[tid];
                uint32_t rank = 0;
                const ulonglong2* b2 = (const ulonglong2*)buf;
                uint32_t Cp = C >> 1;                        // full pairs
                for (uint32_t j = 0; j < Cp; ++j) {
                    ulonglong2 v = b2[j];
                    rank += (uint32_t)(v.x < my) + (uint32_t)(v.y < my);
                }
                if (C & 1u) rank += (uint32_t)(buf[C - 1u] < my);
                if (rank < KNN) {
                    uint32_t myIdx = (uint32_t)my;
                    out[(size_t)gq * KNN + rank] = (float)myIdx;
                    bump1(myIdx, minU, used32, hist, wcnt2);
                }
            }
            if (tid == THREADS - 1)
                bump100(c, minU, used32, hist, wcnt2);
        } else {
            // ===== exact fallback (~5e-3/step): per-warp pop-16 via gmem ====
            uint32_t m1 = FULLM, m2 = FULLM, m3 = FULLM;
            uint32_t j1 = 0, j2 = 0, j3 = 0;
            #pragma unroll
            for (int j = 0; j < 16; ++j) {
                uint32_t v = db[j];
                if (v < m1)      { m3=m2; j3=j2; m2=m1; j2=j1; m1=v; j1=(uint32_t)j; }
                else if (v < m2) { m3=m2; j3=j2; m2=v; j2=(uint32_t)j; }
                else if (v < m3) { m3=v; j3=(uint32_t)j; }
            }
            uint32_t popped = 0;
            #pragma unroll 1
            for (int it = 0; it < KNN; ++it) {
                uint32_t wmin = __reduce_min_sync(FULLM, m1);
                uint32_t cand = (m1 == wmin) ? didx((uint32_t)tid, (int)j1) : FULLM;
                uint32_t imin = __reduce_min_sync(FULLM, cand);
                if (cand == imin) {
                    popped |= 1u << j1;
                    if (m2 != FULLM) { m1=m2; j1=j2; m2=m3; j2=j3; m3=FULLM; }
                    else {
                        m1 = m2 = m3 = FULLM; j1 = j2 = j3 = 0;
                        #pragma unroll
                        for (int j = 0; j < 16; ++j) {
                            uint32_t v = ((popped >> j) & 1u) ? FULLM : db[j];
                            if (v < m1)      { m3=m2; j3=j2; m2=m1; j2=j1; m1=v; j1=(uint32_t)j; }
                            else if (v < m2) { m3=m2; j3=j2; m2=v; j2=(uint32_t)j; }
                            else if (v < m3) { m3=v; j3=(uint32_t)j; }
                        }
                    }
                }
                if (lane == 0)
                    g_fb[(b * NWARP + wid) * KNN + it] =
                        ((unsigned long long)wmin << 32) | imin;
            }
            __syncthreads();     // uniform branch; orders g_fb for warp 0
            if (wid == 0) {
                int pos = 0;
                uint64_t head = g_fb[(b * NWARP + lane) * KNN];
                uint32_t myIdx = 0;
                #pragma unroll 1
                for (int it = 0; it < KNN; ++it) {
                    uint32_t hD = (uint32_t)(head >> 32);
                    uint32_t wmin = __reduce_min_sync(FULLM, hD);
                    uint32_t cand = (hD == wmin) ? (uint32_t)head : FULLM;
                    uint32_t imin = __reduce_min_sync(FULLM, cand);
                    if (cand == imin) {
                        pos++;
                        head = (pos < KNN)
                             ? g_fb[(b * NWARP + lane) * KNN + pos] : ~0ull;
                    }
                    if (lane == it) myIdx = imin;
                }
                if (lane < KNN) {
                    out[(size_t)gq * KNN + lane] = (float)myIdx;
                    bump1(myIdx, minU, used32, hist, wcnt2);
                }
                if (lane == KNN)
                    bump100(c, minU, used32, hist, wcnt2);
            }
        }
        __syncthreads();                                     // bar4
        hb64 = hb64n;
    }
}

extern "C" void kernel_launch(void* const* d_in, const int* in_sizes, int n_in,
                              void* d_out, int out_size) {
    (void)in_sizes; (void)n_in; (void)out_size;
    cudaFuncSetAttribute(snn_kernel,
                         cudaFuncAttributeMaxDynamicSharedMemorySize, SMEM_BYTES);
    snn_kernel<<<BATCH, THREADS, SMEM_BYTES>>>((const float*)d_in[0], (float*)d_out);
}

// round 16
// speedup vs baseline: 1.3316x; 1.0157x over previous
#include <cuda_runtime.h>
#include <cstdint>

// ============================================================================
// SampleNearestNeighborsLayer — exact JAX-semantics replay (bit-exact).
// Per batch b: 4096 sequential steps:
//   minU=min(used); cnt=#(used==minU); r=jax.random.randint(key_q,(),0,cnt)
//   center = r-th least-used point (index order); d_i = ||xyz_i - xyz_c||^2
//   ids = 16 smallest (d,i) lexicographic; used[ids]+=1; used[center]+=100
// Output (float32): idx (8*4096*16) then pts (8*4096*3).
//
// == Round-15 base (best: 13.69 ms) + register-carried minU + published
//    center coords (4 independent LDS at phase-B head instead of a chain). ==
// Phase A incremental (hist + per-warp candidate counts maintained by the 17
// atomic counter updates; full rescan only when hist[minU] empties, ~30x).
// Distances in packed f32x2 (two independent rn ops == scalar, bit-exact).
// Threshold T = max of 16 pair-minima: 16 distinct elements <= T certify
// top-16 in {d<=T}. Per-hit atomic compaction; per-thread LDS.128 rank.
// C > CAP (P~5e-3/step) -> exact fallback.
// ============================================================================

#define NQ      4096
#define NPTS    16384
#define KNN     16
#define BATCH   8
#define THREADS 1024
#define NWARP   32
#define CAP     128
#define SMEM_BYTES 232448
#define FULLM   0xFFFFFFFFu

__device__ uint64_t g_hb64[BATCH * NQ + 8];               // +pad for prefetch
__device__ unsigned long long g_fb[BATCH * NWARP * KNN];  // fallback staging

__device__ __forceinline__ uint32_t rotl32(uint32_t x, int r) {
    return (x << r) | (x >> (32 - r));
}

// Threefry-2x32, 20 rounds (JAX schedule) — verified bit-exact on HW.
__device__ __forceinline__ void tf2x32(uint32_t k0, uint32_t k1,
                                       uint32_t x0, uint32_t x1,
                                       uint32_t& o0, uint32_t& o1) {
    uint32_t ks2 = k0 ^ k1 ^ 0x1BD11BDAu;
    x0 += k0; x1 += k1;
#define TFR(r) { x0 += x1; x1 = rotl32(x1, (r)); x1 ^= x0; }
    TFR(13) TFR(15) TFR(26) TFR(6)
    x0 += k1;  x1 += ks2 + 1u;
    TFR(17) TFR(29) TFR(16) TFR(24)
    x0 += ks2; x1 += k0 + 2u;
    TFR(13) TFR(15) TFR(26) TFR(6)
    x0 += k0;  x1 += k1 + 3u;
    TFR(17) TFR(29) TFR(16) TFR(24)
    x0 += k1;  x1 += ks2 + 4u;
    TFR(13) TFR(15) TFR(26) TFR(6)
    x0 += ks2; x1 += k0 + 5u;
#undef TFR
    o0 = x0; o1 = x1;
}

// used[] as u16 pairs in u32 words; word W stored at usw(W) — conflict-free
// for the per-thread contiguous 8-word scan.
__device__ __forceinline__ uint32_t usw(uint32_t W) { return W ^ ((W >> 5) & 31u); }

// Packed pair distance: d = ((dx*dx + dy*dy) + dz*dz) per lane of the f32x2,
// dx = x + (-cx) (IEEE-identical to __fsub_rn). Each f32x2 op is two
// independent round-to-nearest f32 ops -> bit-exact vs scalar.
__device__ __forceinline__ void dist2pair(uint64_t xx, uint64_t yy, uint64_t zz,
                                          uint64_t ncx, uint64_t ncy, uint64_t ncz,
                                          uint32_t& lo, uint32_t& hi) {
    uint64_t dx, dy, dz, sx, sy, szv, t, d;
    asm("add.rn.f32x2 %0, %1, %2;" : "=l"(dx) : "l"(xx), "l"(ncx));
    asm("add.rn.f32x2 %0, %1, %2;" : "=l"(dy) : "l"(yy), "l"(ncy));
    asm("add.rn.f32x2 %0, %1, %2;" : "=l"(dz) : "l"(zz), "l"(ncz));
    asm("mul.rn.f32x2 %0, %1, %2;" : "=l"(sx) : "l"(dx), "l"(dx));
    asm("mul.rn.f32x2 %0, %1, %2;" : "=l"(sy) : "l"(dy), "l"(dy));
    asm("mul.rn.f32x2 %0, %1, %2;" : "=l"(szv) : "l"(dz), "l"(dz));
    asm("add.rn.f32x2 %0, %1, %2;" : "=l"(t) : "l"(sx), "l"(sy));
    asm("add.rn.f32x2 %0, %1, %2;" : "=l"(d) : "l"(t), "l"(szv));
    asm("mov.b64 {%0, %1}, %2;" : "=r"(lo), "=r"(hi) : "l"(d));
}

// Point index for db[j]: pair p = tid + 1024*(j>>1), point = 2p + (j&1).
__device__ __forceinline__ uint32_t didx(uint32_t tid, int j) {
    return 2u * tid + (((uint32_t)j >> 1) << 11) + ((uint32_t)j & 1u);
}

// used[idx] += 1 with exact hist/wcnt2 bookkeeping (transition counted once
// via the atomic's returned old value; values < 4300 << 65536, no carry).
__device__ __forceinline__ void bump1(uint32_t idx, uint32_t minU,
                                      unsigned int* used32,
                                      unsigned int* hist,
                                      unsigned int* wcnt2) {
    uint32_t sh = (idx & 1u) * 16u;
    uint32_t oldw = atomicAdd(&used32[usw(idx >> 1)], 1u << sh);
    uint32_t ov = (oldw >> sh) & 0xFFFFu;
    if (ov < 64u)      atomicSub(&hist[ov], 1u);
    if (ov + 1u < 64u) atomicAdd(&hist[ov + 1u], 1u);
    if (ov == minU)    atomicSub(&wcnt2[idx >> 9], 1u);
}

__device__ __forceinline__ void bump100(uint32_t idx, uint32_t minU,
                                        unsigned int* used32,
                                        unsigned int* hist,
                                        unsigned int* wcnt2) {
    uint32_t sh = (idx & 1u) * 16u;
    uint32_t oldw = atomicAdd(&used32[usw(idx >> 1)], 100u << sh);
    uint32_t ov = (oldw >> sh) & 0xFFFFu;
    if (ov < 64u)   atomicSub(&hist[ov], 1u);   // ov+100 >= 64 always
    if (ov == minU) atomicSub(&wcnt2[idx >> 9], 1u);
}

extern "C" __global__ void __launch_bounds__(THREADS, 1)
snn_kernel(const float* __restrict__ xyz, float* __restrict__ out) {
    extern __shared__ unsigned char smem[];
    float*        vx     = (float*)smem;                      // 64 KB X
    float*        vy     = (float*)(smem + 65536);            // 64 KB Y
    float*        vz     = (float*)(smem + 131072);           // 64 KB Z
    const uint64_t* px   = (const uint64_t*)smem;             // pair views
    const uint64_t* py   = (const uint64_t*)(smem + 65536);
    const uint64_t* pz   = (const uint64_t*)(smem + 131072);
    unsigned int* used32 = (unsigned int*)(smem + 196608);    // 32 KB
    unsigned char* scr   = smem + 229376;                     // 3 KB
    uint64_t*     buf    = (uint64_t*)scr;                    // [128], 16B align
    unsigned int* hist   = (unsigned int*)(scr + 1024);       // [64]
    unsigned int* wcnt2  = (unsigned int*)(scr + 1280);       // [32]
    unsigned int* wmind  = (unsigned int*)(scr + 1408);       // [32]
    unsigned int* scnt2  = (unsigned int*)(scr + 1536);       // [2] parity
    unsigned int* scen   = (unsigned int*)(scr + 1544);       // center index
    float*        scend  = (float*)(scr + 1552);              // center x,y,z

    const int tid  = threadIdx.x;
    const int b    = blockIdx.x;
    const int lane = tid & 31;
    const int wid  = tid >> 5;

    // ---- init: SoA stage, zero used, RNG bits, phase-A state ----
    const float* g = xyz + (size_t)b * NPTS * 3;
    for (int i = tid; i < NPTS; i += THREADS) {
        vx[i] = g[3*i + 0];
        vy[i] = g[3*i + 1];
        vz[i] = g[3*i + 2];
    }
    for (int i = tid; i < NPTS / 2; i += THREADS) used32[i] = 0u;
    if (tid < 64) hist[tid] = (tid == 0) ? (unsigned)NPTS : 0u;
    if (tid < 32) wcnt2[tid] = NPTS / NWARP;                 // 512 each
    if (tid == 0) { scnt2[0] = 0u; scnt2[1] = 0u; }

    {
        uint32_t bk0, bk1;
        tf2x32(0u, 42u, 0u, (uint32_t)b, bk0, bk1);          // batch key
        for (int q = tid; q < NQ; q += THREADS) {
            uint32_t qk0, qk1, a0, a1, e0, e1, x, y, hb, lb;
            tf2x32(bk0, bk1, 0u, (uint32_t)q, qk0, qk1);     // per-step key
            tf2x32(qk0, qk1, 0u, 0u, a0, a1);                // split[0]
            tf2x32(qk0, qk1, 0u, 1u, e0, e1);                // split[1]
            tf2x32(a0, a1, 0u, 0u, x, y);  hb = x ^ y;
            tf2x32(e0, e1, 0u, 0u, x, y);  lb = x ^ y;
            g_hb64[b*NQ + q] = ((uint64_t)hb << 32) | lb;
        }
    }
    __syncthreads();

    const size_t OUT_PTS = (size_t)BATCH * NQ * KNN;
    uint64_t hb64 = g_hb64[b * NQ];                          // prefetch q=0
    uint32_t minU = 0u;                                      // register-carried

    for (int q = 0; q < NQ; ++q) {
        const int gq = b * NQ + q;

        // ================= Phase A (incremental) =================
        uint32_t cnt = hist[minU];
        if (cnt == 0u) {                                     // rare: ~30 total
            // new minU in (minU, minU+32]: gap <= 29 since min <= mean <= 29
            uint32_t h = hist[minU + 1u + (uint32_t)lane];
            uint32_t mask = __ballot_sync(FULLM, h != 0u);
            uint32_t nm = minU + (uint32_t)__ffs(mask);      // uniform
            uint32_t mm2 = nm * 0x10001u;
            uint32_t vc = 0u;
            #pragma unroll
            for (int k = 0; k < 8; ++k)
                vc += __vseteq2(used32[usw((uint32_t)tid * 8u + (uint32_t)k)], mm2);
            uint32_t cc = (vc & 0xFFFFu) + (vc >> 16);
            cc = __reduce_add_sync(FULLM, cc);
            if (lane == 0) wcnt2[wid] = cc;
            __syncthreads();                                 // rare bar
            minU = nm;                                       // all threads
            cnt = hist[minU];
        }

        // randint (all u32, verified): ((hb%s)*((65536%s)^2%s)+lb%s)%s
        uint32_t rr;
        {
            uint32_t sp = cnt;
            uint32_t hbv = (uint32_t)(hb64 >> 32);
            uint32_t lbv = (uint32_t)hb64;
            uint32_t mlt = 65536u % sp;
            mlt = (mlt * mlt) % sp;
            rr = ((hbv % sp) * mlt + (lbv % sp)) % sp;
        }

        // owner warp: exclusive prefix over wcnt2 via single REDUX
        uint32_t wv = wcnt2[lane];
        uint32_t myPre = __reduce_add_sync(FULLM, (lane < wid) ? wv : 0u);
        uint32_t myCnt = __shfl_sync(FULLM, wv, wid);

        if (rr >= myPre && rr < myPre + myCnt) {             // owner warp only
            uint32_t mm2 = minU * 0x10001u;
            uint32_t pw[8];
            uint32_t vc = 0u;
            #pragma unroll
            for (int k = 0; k < 8; ++k) {
                pw[k] = used32[usw((uint32_t)tid * 8u + (uint32_t)k)];
                vc += __vseteq2(pw[k], mm2);
            }
            uint32_t mi = (vc & 0xFFFFu) + (vc >> 16);
            uint32_t li = mi;
            #pragma unroll
            for (int o = 1; o < 32; o <<= 1) {
                uint32_t v = __shfl_up_sync(FULLM, li, o);
                if (lane >= o) li += v;
            }
            uint32_t need = rr - myPre;
            uint32_t le = li - mi;                           // exclusive
            if (need >= le && need < le + mi) {              // winner lane
                uint32_t nd = need - le;
                uint32_t c = 0; bool done = false;
                #pragma unroll
                for (int k = 0; k < 8; ++k) {
                    if (!done && (pw[k] & 0xFFFFu) == minU) {
                        if (nd == 0) { c = (uint32_t)tid*16u + 2u*k; done = true; }
                        else nd--;
                    }
                    if (!done && (pw[k] >> 16) == minU) {
                        if (nd == 0) { c = (uint32_t)tid*16u + 2u*k + 1u; done = true; }
                        else nd--;
                    }
                }
                float fx = vx[c], fy = vy[c], fz = vz[c];
                *scen = c;
                scend[0] = fx; scend[1] = fy; scend[2] = fz; // publish coords
                size_t pofs = OUT_PTS + (size_t)gq * 3;
                out[pofs + 0] = fx;
                out[pofs + 1] = fy;
                out[pofs + 2] = fz;
            }
        }
        __syncthreads();                                     // bar1

        // ================= Phase B: packed distances =================
        const uint32_t c = *scen;                            // 4 independent LDS
        const float cx = scend[0];
        const float cy = scend[1];
        const float cz = scend[2];
        if (tid == 0) scnt2[(q + 1) & 1] = 0u;               // reset next parity
        uint64_t ncx, ncy, ncz;
        {
            float nx = -cx, ny = -cy, nz = -cz;
            asm("mov.b64 %0, {%1, %1};" : "=l"(ncx) : "f"(nx));
            asm("mov.b64 %0, {%1, %1};" : "=l"(ncy) : "f"(ny));
            asm("mov.b64 %0, {%1, %1};" : "=l"(ncz) : "f"(nz));
        }

        uint32_t db[16];
        #pragma unroll
        for (int jp = 0; jp < 8; ++jp) {
            int p = tid + (jp << 10);                        // pair index
            dist2pair(px[p], py[p], pz[p], ncx, ncy, ncz,
                      db[2*jp], db[2*jp + 1]);
        }
        uint32_t tm = db[0];
        #pragma unroll
        for (int j = 1; j < 16; ++j) tm = min(tm, db[j]);
        tm = __reduce_min_sync(FULLM, tm);
        if (lane == 0) wmind[wid] = tm;

        uint64_t hb64n = g_hb64[gq + 1];                     // prefetch next
        __syncthreads();                                     // bar2

        // ====== Phase C: T = max of 16 pair-minima; compaction ==========
        // pm = min(wmind[i], wmind[i+16]) is an element from disjoint warp
        // domains -> 16 distinct elements <= T -> top-16 subset of {d<=T}.
        uint32_t T;
        {
            uint32_t wl = wmind[lane];
            uint32_t pm = min(wl, __shfl_xor_sync(FULLM, wl, 16));
            T = __reduce_max_sync(FULLM, pm);
        }
        unsigned int* cur = &scnt2[q & 1];
        #pragma unroll
        for (int j = 0; j < 16; ++j) {
            if (db[j] <= T) {
                uint32_t s = atomicAdd(cur, 1u);
                if (s < CAP)
                    buf[s] = ((uint64_t)db[j] << 32) | didx((uint32_t)tid, j);
            }
        }
        __syncthreads();                                     // bar3

        // ====== Phase D: parallel rank (LDS.128 pairs) ==========
        const uint32_t C = scnt2[q & 1];                     // block-uniform
        if (C <= CAP) {
            if ((uint32_t)tid < C) {
                uint64_t my = buf[tid];
                uint32_t rank = 0;
                const ulonglong2* b2 = (const ulonglong2*)buf;
                uint32_t Cp = C >> 1;                        // full pairs
                for (uint32_t j = 0; j < Cp; ++j) {
                    ulonglong2 v = b2[j];
                    rank += (uint32_t)(v.x < my) + (uint32_t)(v.y < my);
                }
                if (C & 1u) rank += (uint32_t)(buf[C - 1u] < my);
                if (rank < KNN) {
                    uint32_t myIdx = (uint32_t)my;
                    out[(size_t)gq * KNN + rank] = (float)myIdx;
                    bump1(myIdx, minU, used32, hist, wcnt2);
                }
            }
            if (tid == THREADS - 1)
                bump100(c, minU, used32, hist, wcnt2);
        } else {
            // ===== exact fallback (~5e-3/step): per-warp pop-16 via gmem ====
            uint32_t m1 = FULLM, m2 = FULLM, m3 = FULLM;
            uint32_t j1 = 0, j2 = 0, j3 = 0;
            #pragma unroll
            for (int j = 0; j < 16; ++j) {
                uint32_t v = db[j];
                if (v < m1)      { m3=m2; j3=j2; m2=m1; j2=j1; m1=v; j1=(uint32_t)j; }
                else if (v < m2) { m3=m2; j3=j2; m2=v; j2=(uint32_t)j; }
                else if (v < m3) { m3=v; j3=(uint32_t)j; }
            }
            uint32_t popped = 0;
            #pragma unroll 1
            for (int it = 0; it < KNN; ++it) {
                uint32_t wmin = __reduce_min_sync(FULLM, m1);
                uint32_t cand = (m1 == wmin) ? didx((uint32_t)tid, (int)j1) : FULLM;
                uint32_t imin = __reduce_min_sync(FULLM, cand);
                if (cand == imin) {
                    popped |= 1u << j1;
                    if (m2 != FULLM) { m1=m2; j1=j2; m2=m3; j2=j3; m3=FULLM; }
                    else {
                        m1 = m2 = m3 = FULLM; j1 = j2 = j3 = 0;
                        #pragma unroll
                        for (int j = 0; j < 16; ++j) {
                            uint32_t v = ((popped >> j) & 1u) ? FULLM : db[j];
                            if (v < m1)      { m3=m2; j3=j2; m2=m1; j2=j1; m1=v; j1=(uint32_t)j; }
                            else if (v < m2) { m3=m2; j3=j2; m2=v; j2=(uint32_t)j; }
                            else if (v < m3) { m3=v; j3=(uint32_t)j; }
                        }
                    }
                }
                if (lane == 0)
                    g_fb[(b * NWARP + wid) * KNN + it] =
                        ((unsigned long long)wmin << 32) | imin;
            }
            __syncthreads();     // uniform branch; orders g_fb for warp 0
            if (wid == 0) {
                int pos = 0;
                uint64_t head = g_fb[(b * NWARP + lane) * KNN];
                uint32_t myIdx = 0;
                #pragma unroll 1
                for (int it = 0; it < KNN; ++it) {
                    uint32_t hD = (uint32_t)(head >> 32);
                    uint32_t wmin = __reduce_min_sync(FULLM, hD);
                    uint32_t cand = (hD == wmin) ? (uint32_t)head : FULLM;
                    uint32_t imin = __reduce_min_sync(FULLM, cand);
                    if (cand == imin) {
                        pos++;
                        head = (pos < KNN)
                             ? g_fb[(b * NWARP + lane) * KNN + pos] : ~0ull;
                    }
                    if (lane == it) myIdx = imin;
                }
                if (lane < KNN) {
                    out[(size_t)gq * KNN + lane] = (float)myIdx;
                    bump1(myIdx, minU, used32, hist, wcnt2);
                }
                if (lane == KNN)
                    bump100(c, minU, used32, hist, wcnt2);
            }
        }
        __syncthreads();                                     // bar4
        hb64 = hb64n;
    }
}

extern "C" void kernel_launch(void* const* d_in, const int* in_sizes, int n_in,
                              void* d_out, int out_size) {
    (void)in_sizes; (void)n_in; (void)out_size;
    cudaFuncSetAttribute(snn_kernel,
                         cudaFuncAttributeMaxDynamicSharedMemorySize, SMEM_BYTES);
    snn_kernel<<<BATCH, THREADS, SMEM_BYTES>>>((const float*)d_in[0], (float*)d_out);
}